// round 1
// baseline (speedup 1.0000x reference)
#include <cuda_runtime.h>
#include <cstdint>

#define TI 128
#define TJ 64
#define SA 132   // padded stride for [64][128] smem arrays
#define SB 68    // padded stride for [64][64]  smem arrays

#define MAXB 8
#define MAXN 2048

// ---------------- scratch (no allocation allowed) ----------------
__device__ float g_embn [MAXB * MAXN * 64];
__device__ float g_sq   [MAXB * MAXN];
__device__ float g_deg  [MAXB * MAXN];
__device__ float g_opadj[MAXB * MAXN * 64];
__device__ float g_upd  [MAXB * MAXN * 64];

// ---------------- Kernel 1: masked mean/var, emb_n, sq ----------------
__global__ __launch_bounds__(256) void knorm(const float* __restrict__ emb,
                                             const int* __restrict__ nb, int N)
{
    __shared__ float ssum[4][64], ssq[4][64];
    __shared__ float smean[64], srstd[64];

    const int b = blockIdx.x;
    const int t = threadIdx.x;
    const int f = t & 63, g = t >> 6;
    const float* E = emb + (size_t)b * N * 64;

    float s = 0.f, q = 0.f;
    for (int i = g; i < N; i += 4) {
        float v = E[(size_t)i * 64 + f];   // emb is pre-masked (zeros beyond nb)
        s += v; q += v * v;
    }
    ssum[g][f] = s; ssq[g][f] = q;
    __syncthreads();

    if (t < 64) {
        float S = ssum[0][t] + ssum[1][t] + ssum[2][t] + ssum[3][t];
        float Q = ssq[0][t] + ssq[1][t] + ssq[2][t] + ssq[3][t];
        float cnt  = fmaxf((float)nb[b], 1.f);
        float mean = S / cnt;
        float var  = fmaxf(Q / cnt - mean * mean, 0.f);
        smean[t] = mean;
        srstd[t] = rsqrtf(var + 1e-5f);
    }
    __syncthreads();

    const int w = t >> 5, lane = t & 31;
    const int nbv = nb[b];
    float* EN = g_embn + (size_t)b * N * 64;
    for (int i = w; i < N; i += 8) {
        float e0 = E[(size_t)i * 64 + lane];
        float e1 = E[(size_t)i * 64 + lane + 32];
        float m = (i < nbv) ? 1.f : 0.f;
        EN[(size_t)i * 64 + lane]      = (e0 - smean[lane])      * srstd[lane]      * m;
        EN[(size_t)i * 64 + lane + 32] = (e1 - smean[lane + 32]) * srstd[lane + 32] * m;
        float sq = e0 * e0 + e1 * e1;
        #pragma unroll
        for (int o = 16; o; o >>= 1) sq += __shfl_down_sync(0xffffffffu, sq, o);
        if (lane == 0) g_sq[b * N + i] = sq;
    }
}

// ---------------- Kernel 2: fused Gram -> kernel/combine/mask -> adj/deg -> SpMM ----------------
__global__ __launch_bounds__(256) void kadj(
    const float* __restrict__ emb, const float* __restrict__ adj_in,
    const int* __restrict__ nb, const float* __restrict__ sigma_p,
    const float* __restrict__ cw, float* __restrict__ adj_out, int N)
{
    extern __shared__ float sm[];
    float* sAT  = sm;                 // [64][SA]  emb_i transposed [f][i]
    float* sBT  = sAT + 64 * SA;      // [64][SB]  emb_j transposed [f][j]
    float* sBn  = sBT + 64 * SB;      // [TJ][SB]  emb_n_j [j][f]
    float* sST  = sBn + TJ * SB;      // [TJ][SA]  adj tile transposed [j][i]
    float* ssqj = sST + TJ * SA;      // [TJ]
    float* sdeg = ssqj + TJ;          // [TI]

    const int b = blockIdx.y;
    const int i_base = blockIdx.x * TI;
    const int t = threadIdx.x;
    const int tj = t & 15, ti = t >> 4;
    const int j0 = tj * 4, i0 = ti * 8;

    const float inv_sigma = 1.0f / sigma_p[0];
    const float w0 = cw[0], w1 = cw[1];
    const int nbv = nb[b];

    const float* E   = emb    + (size_t)b * N * 64;
    const float* En  = g_embn + (size_t)b * N * 64;
    const float* Ain = adj_in + (size_t)b * N * N;
    float*       Aout= adj_out+ (size_t)b * N * N;

    // load emb_i tile transposed (once per CTA)
    for (int idx = t; idx < TI * 64; idx += 256) {
        int i = idx >> 6, f = idx & 63;
        sAT[f * SA + i] = E[(size_t)(i_base + i) * 64 + f];
    }
    if (t < TI) sdeg[t] = 0.f;

    float sqi[8];
    #pragma unroll
    for (int r = 0; r < 8; r++) sqi[r] = g_sq[b * N + i_base + i0 + r];

    float opa[8][4];
    #pragma unroll
    for (int r = 0; r < 8; r++)
        #pragma unroll
        for (int c = 0; c < 4; c++) opa[r][c] = 0.f;
    float degp[8];
    #pragma unroll
    for (int r = 0; r < 8; r++) degp[r] = 0.f;

    for (int jt = 0; jt < N; jt += TJ) {
        __syncthreads();   // previous iter's gemm2 done with sBn/sST; sBT free

        for (int idx = t; idx < TJ * 64; idx += 256) {
            int j = idx >> 6, f = idx & 63;
            sBT[f * SB + j] = E[(size_t)(jt + j) * 64 + f];
        }
        for (int idx = t; idx < TJ * 64; idx += 256) {
            int j = idx >> 6, f = idx & 63;
            sBn[j * SB + f] = En[(size_t)(jt + j) * 64 + f];
        }
        if (t < TJ) ssqj[t] = g_sq[b * N + jt + t];

        // prefetch adj_in for this tile (latency hides under gemm1)
        float4 ain[8];
        #pragma unroll
        for (int r = 0; r < 8; r++)
            ain[r] = *(const float4*)&Ain[(size_t)(i_base + i0 + r) * N + jt + j0];

        __syncthreads();

        // ---- gemm1: S = emb_i . emb_j^T (8x4 per thread, k over features) ----
        float S[8][4];
        #pragma unroll
        for (int r = 0; r < 8; r++)
            #pragma unroll
            for (int c = 0; c < 4; c++) S[r][c] = 0.f;

        #pragma unroll 8
        for (int k = 0; k < 64; k++) {
            float4 a0 = *(const float4*)&sAT[k * SA + i0];
            float4 a1 = *(const float4*)&sAT[k * SA + i0 + 4];
            float4 bv = *(const float4*)&sBT[k * SB + j0];
            float a[8] = {a0.x, a0.y, a0.z, a0.w, a1.x, a1.y, a1.z, a1.w};
            float bb[4] = {bv.x, bv.y, bv.z, bv.w};
            #pragma unroll
            for (int r = 0; r < 8; r++)
                #pragma unroll
                for (int c = 0; c < 4; c++) S[r][c] += a[r] * bb[c];
        }

        // ---- elementwise: RBF kernel, combine, mask; write adj; accumulate deg ----
        #pragma unroll
        for (int r = 0; r < 8; r++) {
            const int gi = i_base + i0 + r;
            const float mi = (gi < nbv) ? 1.f : 0.f;
            const float si = sqi[r];
            float av[4];
            #pragma unroll
            for (int c = 0; c < 4; c++) {
                const int gj = jt + j0 + c;
                float d2 = si + ssqj[j0 + c] - 2.f * S[r][c];
                float ker = __expf(-fmaxf(d2, 0.f) * inv_sigma);
                float m = (gj < nbv) ? mi : 0.f;
                float xin = (c == 0) ? ain[r].x : (c == 1) ? ain[r].y
                          : (c == 2) ? ain[r].z : ain[r].w;
                av[c] = (w0 * xin + w1 * ker) * m;
                degp[r] += av[c];
                S[r][c] = av[c];
            }
            *(float4*)&Aout[(size_t)gi * N + jt + j0] =
                make_float4(av[0], av[1], av[2], av[3]);
        }

        // store adj tile transposed for gemm2
        #pragma unroll
        for (int c = 0; c < 4; c++) {
            *(float4*)&sST[(j0 + c) * SA + i0] =
                make_float4(S[0][c], S[1][c], S[2][c], S[3][c]);
            *(float4*)&sST[(j0 + c) * SA + i0 + 4] =
                make_float4(S[4][c], S[5][c], S[6][c], S[7][c]);
        }
        __syncthreads();

        // ---- gemm2: op_adj += adj_tile @ emb_n_j (k over local j) ----
        #pragma unroll 8
        for (int k = 0; k < TJ; k++) {
            float4 a0 = *(const float4*)&sST[k * SA + i0];
            float4 a1 = *(const float4*)&sST[k * SA + i0 + 4];
            float4 bv = *(const float4*)&sBn[k * SB + j0];
            float a[8] = {a0.x, a0.y, a0.z, a0.w, a1.x, a1.y, a1.z, a1.w};
            float bb[4] = {bv.x, bv.y, bv.z, bv.w};
            #pragma unroll
            for (int r = 0; r < 8; r++)
                #pragma unroll
                for (int c = 0; c < 4; c++) opa[r][c] += a[r] * bb[c];
        }
    }

    // epilogue: deg reduction + op_adj writeback
    #pragma unroll
    for (int r = 0; r < 8; r++) atomicAdd(&sdeg[i0 + r], degp[r]);
    __syncthreads();
    if (t < TI) g_deg[b * N + i_base + t] = sdeg[t];

    #pragma unroll
    for (int r = 0; r < 8; r++)
        *(float4*)&g_opadj[(size_t)(b * N + i_base + i0 + r) * 64 + j0] =
            make_float4(opa[r][0], opa[r][1], opa[r][2], opa[r][3]);
}

// ---------------- Kernel 3: node-wise MLP stage (x = [xa(*scale), xb]) @ W + b ----------------
__global__ __launch_bounds__(256) void kmlp(
    const float* __restrict__ xa, const float* __restrict__ xb,
    const float* __restrict__ scale, const float* __restrict__ W,
    const float* __restrict__ bias, float* __restrict__ out,
    int do_relu, int BN)
{
    __shared__ float sW[128 * 64];
    __shared__ float sx[16 * 132];
    __shared__ float sb[64];

    const int t = threadIdx.x;
    for (int idx = t; idx < 128 * 64; idx += 256) sW[idx] = W[idx];
    if (t < 64) sb[t] = bias[t];

    const int node0 = blockIdx.x * 16;
    for (int idx = t; idx < 16 * 128; idx += 256) {
        int n = idx >> 7, k = idx & 127;
        int gn = node0 + n;
        float v;
        if (k < 64) {
            v = xa[(size_t)gn * 64 + k];
            if (scale) v *= scale[gn];
        } else {
            v = xb[(size_t)gn * 64 + (k - 64)];
        }
        sx[n * 132 + k] = v;
    }
    __syncthreads();

    const int n = t >> 4, f0 = (t & 15) * 4;
    float acc0 = 0.f, acc1 = 0.f, acc2 = 0.f, acc3 = 0.f;
    #pragma unroll 8
    for (int k = 0; k < 128; k++) {
        float xv = sx[n * 132 + k];
        float4 wv = *(const float4*)&sW[k * 64 + f0];
        acc0 += xv * wv.x; acc1 += xv * wv.y;
        acc2 += xv * wv.z; acc3 += xv * wv.w;
    }
    acc0 += sb[f0]; acc1 += sb[f0 + 1]; acc2 += sb[f0 + 2]; acc3 += sb[f0 + 3];
    if (do_relu) {
        acc0 = fmaxf(acc0, 0.f); acc1 = fmaxf(acc1, 0.f);
        acc2 = fmaxf(acc2, 0.f); acc3 = fmaxf(acc3, 0.f);
    }
    const int gn = node0 + n;
    *(float4*)&out[(size_t)gn * 64 + f0] = make_float4(acc0, acc1, acc2, acc3);
}

// ---------------- launch ----------------
extern "C" void kernel_launch(void* const* d_in, const int* in_sizes, int n_in,
                              void* d_out, int out_size)
{
    const float* emb_in = (const float*)d_in[0];
    const float* adj_in = (const float*)d_in[1];
    // d_in[2] adj_mask: intentionally unused (recomputed from batch_nb_nodes)
    const int*   nb     = (const int*)d_in[3];
    const float* sigma  = (const float*)d_in[4];
    const float* cw     = (const float*)d_in[5];
    const float* convW  = (const float*)d_in[6];
    const float* convb  = (const float*)d_in[7];
    const float* nuW    = (const float*)d_in[8];
    const float* nub    = (const float*)d_in[9];

    const int B = in_sizes[3];
    const int N = in_sizes[0] / (B * 64);

    float* out_emb = (float*)d_out;                       // (B,N,64)
    float* out_adj = out_emb + (size_t)B * N * 64;        // (B,N,N)

    float *p_embn, *p_opadj, *p_deg, *p_upd;
    cudaGetSymbolAddress((void**)&p_embn,  g_embn);
    cudaGetSymbolAddress((void**)&p_opadj, g_opadj);
    cudaGetSymbolAddress((void**)&p_deg,   g_deg);
    cudaGetSymbolAddress((void**)&p_upd,   g_upd);

    knorm<<<B, 256>>>(emb_in, nb, N);

    const size_t smemB =
        (size_t)(64 * SA + 64 * SB + TJ * SB + TJ * SA + TJ + TI) * sizeof(float);
    cudaFuncSetAttribute(kadj, cudaFuncAttributeMaxDynamicSharedMemorySize, (int)smemB);
    kadj<<<dim3(N / TI, B), 256, smemB>>>(emb_in, adj_in, nb, sigma, cw, out_adj, N);

    kmlp<<<(B * N) / 16, 256>>>(p_embn, p_opadj, p_deg, convW, convb, p_upd, 0, B * N);
    kmlp<<<(B * N) / 16, 256>>>(emb_in, p_upd, nullptr, nuW, nub, out_emb, 1, B * N);
}

// round 2
// speedup vs baseline: 1.6425x; 1.6425x over previous
#include <cuda_runtime.h>
#include <cstdint>

#define MAXB 8
#define MAXN 2048

// ---------------- scratch ----------------
__device__ float g_embn [MAXB * MAXN * 64];
__device__ float g_sq   [MAXB * MAXN];
__device__ float g_deg  [MAXB * MAXN];
__device__ float g_opadj[MAXB * MAXN * 64];

__device__ __forceinline__ uint32_t f2tf(float x) {
    uint32_t r;
    asm("cvt.rna.tf32.f32 %0, %1;" : "=r"(r) : "f"(x));
    return r;
}

#define MMA_TF32(d, a0, a1, a2, a3, b0, b1)                                  \
    asm volatile(                                                            \
        "mma.sync.aligned.m16n8k8.row.col.f32.tf32.tf32.f32 "                \
        "{%0,%1,%2,%3}, {%4,%5,%6,%7}, {%8,%9}, {%0,%1,%2,%3};\n"            \
        : "+f"(d[0]), "+f"(d[1]), "+f"(d[2]), "+f"(d[3])                     \
        : "r"(a0), "r"(a1), "r"(a2), "r"(a3), "r"(b0), "r"(b1))

// ---------------- Kernel 1: masked mean/var, emb_n, sq ----------------
__global__ __launch_bounds__(256) void knorm(const float* __restrict__ emb,
                                             const int* __restrict__ nb, int N)
{
    __shared__ float ssum[4][64], ssq[4][64];
    __shared__ float smean[64], srstd[64];

    const int b = blockIdx.x;
    const int t = threadIdx.x;
    const int f = t & 63, g = t >> 6;
    const float* E = emb + (size_t)b * N * 64;

    float s = 0.f, q = 0.f;
    for (int i = g; i < N; i += 4) {
        float v = E[(size_t)i * 64 + f];
        s += v; q += v * v;
    }
    ssum[g][f] = s; ssq[g][f] = q;
    __syncthreads();

    if (t < 64) {
        float S = ssum[0][t] + ssum[1][t] + ssum[2][t] + ssum[3][t];
        float Q = ssq[0][t] + ssq[1][t] + ssq[2][t] + ssq[3][t];
        float cnt  = fmaxf((float)nb[b], 1.f);
        float mean = S / cnt;
        float var  = fmaxf(Q / cnt - mean * mean, 0.f);
        smean[t] = mean;
        srstd[t] = rsqrtf(var + 1e-5f);
    }
    __syncthreads();

    const int w = t >> 5, lane = t & 31;
    const int nbv = nb[b];
    float* EN = g_embn + (size_t)b * N * 64;
    for (int i = w; i < N; i += 8) {
        float e0 = E[(size_t)i * 64 + lane];
        float e1 = E[(size_t)i * 64 + lane + 32];
        float m = (i < nbv) ? 1.f : 0.f;
        EN[(size_t)i * 64 + lane]      = (e0 - smean[lane])      * srstd[lane]      * m;
        EN[(size_t)i * 64 + lane + 32] = (e1 - smean[lane + 32]) * srstd[lane + 32] * m;
        float sq = e0 * e0 + e1 * e1;
        #pragma unroll
        for (int o = 16; o; o >>= 1) sq += __shfl_down_sync(0xffffffffu, sq, o);
        if (lane == 0) g_sq[b * N + i] = sq;
    }
}

// ---------------- Kernel 2: fused tensor-core Gram -> eltwise -> adj/deg -> SpMM ----------------
// CTA: 64 i-rows, loops j in 64-tiles. 8 warps: warp (r=w>>1, c=w&1):
// rows 16r..16r+15, cols 32c..32c+31 (cols = j for gemm1, f for gemm2).
#define SEJ 68
#define SEN 72
#define SSS 68

__global__ __launch_bounds__(256, 2) void kadj(
    const float* __restrict__ emb, const float* __restrict__ adj_in,
    const int* __restrict__ nb, const float* __restrict__ sigma_p,
    const float* __restrict__ cw, float* __restrict__ adj_out, int N)
{
    extern __shared__ float sm[];
    uint32_t* sEj = (uint32_t*)sm;                     // [64][SEJ] emb_j  (tf32 bits)
    uint32_t* sEn = (uint32_t*)(sm + 64 * SEJ);        // [64][SEN] embn_j (tf32 bits)
    uint32_t* sS  = (uint32_t*)(sm + 64 * (SEJ + SEN));// [64][SSS] adj tile (tf32 bits)
    float* ssqj = sm + 64 * (SEJ + SEN + SSS);         // [64]
    float* sdeg = ssqj + 64;                           // [64]

    const int b = blockIdx.y;
    const int ibase = blockIdx.x * 64;
    const int t = threadIdx.x;
    const int w = t >> 5, lane = t & 31;
    const int rowb = (w >> 1) * 16, colb = (w & 1) * 32;
    const int g = lane >> 2, tg = lane & 3;

    const float inv_sigma = 1.0f / sigma_p[0];
    const float w0 = cw[0], w1 = cw[1];
    const int nbv = nb[b];

    const float* E    = emb     + (size_t)b * N * 64;
    const float* En   = g_embn  + (size_t)b * N * 64;
    const float* Ain  = adj_in  + (size_t)b * N * N;
    float*       Aout = adj_out + (size_t)b * N * N;

    const int gi0 = ibase + rowb + g;
    const int gi1 = gi0 + 8;

    // A fragments for gemm1 (emb_i) — loaded once, reused for all j-tiles
    uint32_t aF[8][4];
    #pragma unroll
    for (int ks = 0; ks < 8; ks++) {
        aF[ks][0] = f2tf(E[(size_t)gi0 * 64 + ks * 8 + tg]);
        aF[ks][1] = f2tf(E[(size_t)gi1 * 64 + ks * 8 + tg]);
        aF[ks][2] = f2tf(E[(size_t)gi0 * 64 + ks * 8 + tg + 4]);
        aF[ks][3] = f2tf(E[(size_t)gi1 * 64 + ks * 8 + tg + 4]);
    }
    const float sqi0 = g_sq[b * N + gi0];
    const float sqi1 = g_sq[b * N + gi1];
    if (t < 64) sdeg[t] = 0.f;

    float opa[4][4];
    #pragma unroll
    for (int n = 0; n < 4; n++)
        #pragma unroll
        for (int k = 0; k < 4; k++) opa[n][k] = 0.f;
    float dg0 = 0.f, dg1 = 0.f;

    for (int jt = 0; jt < N; jt += 64) {
        __syncthreads();   // prev gemm2 done reading sEn/sS

        // stage emb_j / embn_j tiles (convert to tf32 once)
        for (int idx = t; idx < 1024; idx += 256) {
            const int j = idx >> 4, f4 = (idx & 15) * 4;
            float4 v = *(const float4*)&E[(size_t)(jt + j) * 64 + f4];
            sEj[j * SEJ + f4 + 0] = f2tf(v.x);
            sEj[j * SEJ + f4 + 1] = f2tf(v.y);
            sEj[j * SEJ + f4 + 2] = f2tf(v.z);
            sEj[j * SEJ + f4 + 3] = f2tf(v.w);
            float4 u = *(const float4*)&En[(size_t)(jt + j) * 64 + f4];
            sEn[j * SEN + f4 + 0] = f2tf(u.x);
            sEn[j * SEN + f4 + 1] = f2tf(u.y);
            sEn[j * SEN + f4 + 2] = f2tf(u.z);
            sEn[j * SEN + f4 + 3] = f2tf(u.w);
        }
        if (t < 64) ssqj[t] = g_sq[b * N + jt + t];
        __syncthreads();

        // ---- gemm1: S = emb_i . emb_j^T ----
        float S[4][4];
        #pragma unroll
        for (int n = 0; n < 4; n++)
            #pragma unroll
            for (int k = 0; k < 4; k++) S[n][k] = 0.f;

        #pragma unroll
        for (int nt = 0; nt < 4; nt++) {
            const int n = colb + nt * 8;
            #pragma unroll
            for (int ks = 0; ks < 8; ks++) {
                uint32_t b0 = sEj[(n + g) * SEJ + ks * 8 + tg];
                uint32_t b1 = sEj[(n + g) * SEJ + ks * 8 + tg + 4];
                MMA_TF32(S[nt], aF[ks][0], aF[ks][1], aF[ks][2], aF[ks][3], b0, b1);
            }
        }

        // ---- eltwise: RBF, combine, mask; write adj; stash tf32 S tile; deg ----
        #pragma unroll
        for (int nt = 0; nt < 4; nt++) {
            const int jl = colb + nt * 8 + 2 * tg;
            const int gj = jt + jl;
            const float sqj0 = ssqj[jl], sqj1 = ssqj[jl + 1];
            float2 a01 = *(const float2*)&Ain[(size_t)gi0 * N + gj];
            float2 a23 = *(const float2*)&Ain[(size_t)gi1 * N + gj];
            const float mi0 = (gi0 < nbv) ? 1.f : 0.f;
            const float mi1 = (gi1 < nbv) ? 1.f : 0.f;
            const float mj0 = (gj     < nbv) ? 1.f : 0.f;
            const float mj1 = (gj + 1 < nbv) ? 1.f : 0.f;

            float v00 = (w0 * a01.x + w1 * __expf(-fmaxf(sqi0 + sqj0 - 2.f * S[nt][0], 0.f) * inv_sigma)) * (mi0 * mj0);
            float v01 = (w0 * a01.y + w1 * __expf(-fmaxf(sqi0 + sqj1 - 2.f * S[nt][1], 0.f) * inv_sigma)) * (mi0 * mj1);
            float v10 = (w0 * a23.x + w1 * __expf(-fmaxf(sqi1 + sqj0 - 2.f * S[nt][2], 0.f) * inv_sigma)) * (mi1 * mj0);
            float v11 = (w0 * a23.y + w1 * __expf(-fmaxf(sqi1 + sqj1 - 2.f * S[nt][3], 0.f) * inv_sigma)) * (mi1 * mj1);

            dg0 += v00 + v01;
            dg1 += v10 + v11;

            *(float2*)&Aout[(size_t)gi0 * N + gj] = make_float2(v00, v01);
            *(float2*)&Aout[(size_t)gi1 * N + gj] = make_float2(v10, v11);

            const int il0 = rowb + g;
            sS[il0 * SSS + jl]           = f2tf(v00);
            sS[il0 * SSS + jl + 1]       = f2tf(v01);
            sS[(il0 + 8) * SSS + jl]     = f2tf(v10);
            sS[(il0 + 8) * SSS + jl + 1] = f2tf(v11);
        }
        __syncthreads();

        // ---- gemm2: op_adj += adj_tile @ embn_j ----
        #pragma unroll
        for (int ks = 0; ks < 8; ks++) {
            uint32_t A0 = sS[(rowb + g)     * SSS + ks * 8 + tg];
            uint32_t A1 = sS[(rowb + g + 8) * SSS + ks * 8 + tg];
            uint32_t A2 = sS[(rowb + g)     * SSS + ks * 8 + tg + 4];
            uint32_t A3 = sS[(rowb + g + 8) * SSS + ks * 8 + tg + 4];
            #pragma unroll
            for (int nt = 0; nt < 4; nt++) {
                const int nf = colb + nt * 8;
                uint32_t B0 = sEn[(ks * 8 + tg)     * SEN + nf + g];
                uint32_t B1 = sEn[(ks * 8 + tg + 4) * SEN + nf + g];
                MMA_TF32(opa[nt], A0, A1, A2, A3, B0, B1);
            }
        }
    }

    // ---- epilogue: deg reduce + op_adj writeback ----
    dg0 += __shfl_xor_sync(0xffffffffu, dg0, 1);
    dg0 += __shfl_xor_sync(0xffffffffu, dg0, 2);
    dg1 += __shfl_xor_sync(0xffffffffu, dg1, 1);
    dg1 += __shfl_xor_sync(0xffffffffu, dg1, 2);
    if (tg == 0) {
        atomicAdd(&sdeg[rowb + g], dg0);
        atomicAdd(&sdeg[rowb + g + 8], dg1);
    }
    __syncthreads();
    if (t < 64) g_deg[b * N + ibase + t] = sdeg[t];

    #pragma unroll
    for (int nt = 0; nt < 4; nt++) {
        const int f0 = colb + nt * 8 + 2 * tg;
        *(float2*)&g_opadj[(size_t)(b * N + gi0) * 64 + f0] = make_float2(opa[nt][0], opa[nt][1]);
        *(float2*)&g_opadj[(size_t)(b * N + gi1) * 64 + f0] = make_float2(opa[nt][2], opa[nt][3]);
    }
}

// ---------------- Kernel 3: fused 2-stage MLP, one warp per node ----------------
// stage1: x1 = [deg*emb_n, op_adj] (128) @ W1 + b1 -> upd (64)
// stage2: out = relu([emb_in, upd] (128) @ W2 + b2)
__global__ __launch_bounds__(256, 2) void knn(
    const float* __restrict__ embn, const float* __restrict__ opadj,
    const float* __restrict__ deg,  const float* __restrict__ emb_in,
    const float* __restrict__ W1,   const float* __restrict__ b1,
    const float* __restrict__ W2,   const float* __restrict__ b2,
    float* __restrict__ out)
{
    extern __shared__ float smn[];
    float* sW1 = smn;               // [128*64]
    float* sW2 = sW1 + 128 * 64;    // [128*64]
    float* sb1 = sW2 + 128 * 64;    // [64]
    float* sb2 = sb1 + 64;          // [64]
    float* sx  = sb2 + 64;          // [8][132]

    const int t = threadIdx.x;
    const int w = t >> 5, lane = t & 31;

    for (int idx = t; idx < 2048; idx += 256) {
        *(float4*)&sW1[idx * 4] = *(const float4*)&W1[idx * 4];
        *(float4*)&sW2[idx * 4] = *(const float4*)&W2[idx * 4];
    }
    if (t < 64) { sb1[t] = b1[t]; sb2[t] = b2[t]; }
    __syncthreads();

    float* x = sx + w * 132;
    const int node0 = blockIdx.x * 64 + w * 8;

    for (int it = 0; it < 8; it++) {
        const int gn = node0 + it;
        const float dg = deg[gn];

        x[lane]      = dg * embn[(size_t)gn * 64 + lane];
        x[lane + 32] = dg * embn[(size_t)gn * 64 + lane + 32];
        x[lane + 64] = opadj[(size_t)gn * 64 + lane];
        x[lane + 96] = opadj[(size_t)gn * 64 + lane + 32];
        __syncwarp();

        float acc0 = sb1[2 * lane], acc1 = sb1[2 * lane + 1];
        #pragma unroll 8
        for (int k = 0; k < 128; k += 4) {
            float4 xv = *(const float4*)&x[k];
            float2 w0v = *(const float2*)&sW1[(k + 0) * 64 + 2 * lane];
            float2 w1v = *(const float2*)&sW1[(k + 1) * 64 + 2 * lane];
            float2 w2v = *(const float2*)&sW1[(k + 2) * 64 + 2 * lane];
            float2 w3v = *(const float2*)&sW1[(k + 3) * 64 + 2 * lane];
            acc0 += xv.x * w0v.x + xv.y * w1v.x + xv.z * w2v.x + xv.w * w3v.x;
            acc1 += xv.x * w0v.y + xv.y * w1v.y + xv.z * w2v.y + xv.w * w3v.y;
        }
        __syncwarp();

        x[lane]          = emb_in[(size_t)gn * 64 + lane];
        x[lane + 32]     = emb_in[(size_t)gn * 64 + lane + 32];
        x[64 + 2 * lane]     = acc0;
        x[64 + 2 * lane + 1] = acc1;
        __syncwarp();

        float o0 = sb2[2 * lane], o1 = sb2[2 * lane + 1];
        #pragma unroll 8
        for (int k = 0; k < 128; k += 4) {
            float4 xv = *(const float4*)&x[k];
            float2 w0v = *(const float2*)&sW2[(k + 0) * 64 + 2 * lane];
            float2 w1v = *(const float2*)&sW2[(k + 1) * 64 + 2 * lane];
            float2 w2v = *(const float2*)&sW2[(k + 2) * 64 + 2 * lane];
            float2 w3v = *(const float2*)&sW2[(k + 3) * 64 + 2 * lane];
            o0 += xv.x * w0v.x + xv.y * w1v.x + xv.z * w2v.x + xv.w * w3v.x;
            o1 += xv.x * w0v.y + xv.y * w1v.y + xv.z * w2v.y + xv.w * w3v.y;
        }
        o0 = fmaxf(o0, 0.f);
        o1 = fmaxf(o1, 0.f);
        *(float2*)&out[(size_t)gn * 64 + 2 * lane] = make_float2(o0, o1);
        __syncwarp();
    }
}

// ---------------- launch ----------------
extern "C" void kernel_launch(void* const* d_in, const int* in_sizes, int n_in,
                              void* d_out, int out_size)
{
    const float* emb_in = (const float*)d_in[0];
    const float* adj_in = (const float*)d_in[1];
    // d_in[2] adj_mask: unused (recomputed from batch_nb_nodes)
    const int*   nb     = (const int*)d_in[3];
    const float* sigma  = (const float*)d_in[4];
    const float* cw     = (const float*)d_in[5];
    const float* convW  = (const float*)d_in[6];
    const float* convb  = (const float*)d_in[7];
    const float* nuW    = (const float*)d_in[8];
    const float* nub    = (const float*)d_in[9];

    const int B = in_sizes[3];
    const int N = in_sizes[0] / (B * 64);

    float* out_emb = (float*)d_out;                    // (B,N,64)
    float* out_adj = out_emb + (size_t)B * N * 64;     // (B,N,N)

    float *p_embn, *p_opadj, *p_deg;
    cudaGetSymbolAddress((void**)&p_embn,  g_embn);
    cudaGetSymbolAddress((void**)&p_opadj, g_opadj);
    cudaGetSymbolAddress((void**)&p_deg,   g_deg);

    knorm<<<B, 256>>>(emb_in, nb, N);

    const size_t smemAdj = (size_t)(64 * (SEJ + SEN + SSS) + 128) * sizeof(float);
    static int cfg_done = 0;
    cudaFuncSetAttribute(kadj, cudaFuncAttributeMaxDynamicSharedMemorySize, (int)smemAdj);
    kadj<<<dim3(N / 64, B), 256, smemAdj>>>(emb_in, adj_in, nb, sigma, cw, out_adj, N);

    const size_t smemNN = (size_t)(2 * 128 * 64 + 128 + 8 * 132) * sizeof(float);
    cudaFuncSetAttribute(knn, cudaFuncAttributeMaxDynamicSharedMemorySize, (int)smemNN);
    knn<<<(B * N) / 64, 256, smemNN>>>(p_embn, p_opadj, p_deg, emb_in,
                                       convW, convb, nuW, nub, out_emb);
    (void)cfg_done;
}

// round 4
// speedup vs baseline: 2.6222x; 1.5965x over previous
#include <cuda_runtime.h>
#include <cstdint>

#define MAXB 8
#define MAXN 2048

// ---------------- scratch ----------------
__device__ float g_embn [MAXB * MAXN * 64];
__device__ float g_sq   [MAXB * MAXN];
__device__ float g_deg  [MAXB * MAXN];
__device__ float g_opadj[MAXB * MAXN * 64];
__device__ float g_part [MAXB * 8 * 128];
__device__ float g_stats[MAXB * 128];

__device__ __forceinline__ uint32_t f2tf(float x) {
    uint32_t r;
    asm("cvt.rna.tf32.f32 %0, %1;" : "=r"(r) : "f"(x));
    return r;
}

__device__ __forceinline__ void cpa16(uint32_t saddr, const void* gaddr) {
    asm volatile("cp.async.cg.shared.global [%0], [%1], 16;\n"
                 :: "r"(saddr), "l"(gaddr));
}

#define MMA_TF32(d, a0, a1, a2, a3, b0, b1)                                  \
    asm volatile(                                                            \
        "mma.sync.aligned.m16n8k8.row.col.f32.tf32.tf32.f32 "                \
        "{%0,%1,%2,%3}, {%4,%5,%6,%7}, {%8,%9}, {%0,%1,%2,%3};\n"            \
        : "+f"(d[0]), "+f"(d[1]), "+f"(d[2]), "+f"(d[3])                     \
        : "r"(a0), "r"(a1), "r"(a2), "r"(a3), "r"(b0), "r"(b1))

// ---------------- Kernel 1a: partial sums (grid B x 8) ----------------
__global__ __launch_bounds__(256) void kstat1(const float* __restrict__ emb, int N)
{
    __shared__ float ssum[4][64], ssq[4][64];
    const int b = blockIdx.x, slice = blockIdx.y;
    const int t = threadIdx.x, f = t & 63, g = t >> 6;
    const int r0 = slice * (N / 8), r1 = r0 + N / 8;
    const float* E = emb + (size_t)b * N * 64;

    float s = 0.f, q = 0.f;
    for (int i = r0 + g; i < r1; i += 4) {
        float v = E[(size_t)i * 64 + f];   // emb pre-masked beyond nb
        s += v; q += v * v;
    }
    ssum[g][f] = s; ssq[g][f] = q;
    __syncthreads();
    if (t < 64) {
        g_part[(b * 8 + slice) * 128 + t]      = ssum[0][t] + ssum[1][t] + ssum[2][t] + ssum[3][t];
        g_part[(b * 8 + slice) * 128 + 64 + t] = ssq[0][t]  + ssq[1][t]  + ssq[2][t]  + ssq[3][t];
    }
}

// ---------------- Kernel 1b: finish stats (grid B, block 64) ----------------
__global__ __launch_bounds__(64) void kstat2(const int* __restrict__ nb)
{
    const int b = blockIdx.x, t = threadIdx.x;
    float S = 0.f, Q = 0.f;
    #pragma unroll
    for (int s = 0; s < 8; s++) {
        S += g_part[(b * 8 + s) * 128 + t];
        Q += g_part[(b * 8 + s) * 128 + 64 + t];
    }
    float cnt  = fmaxf((float)nb[b], 1.f);
    float mean = S / cnt;
    float var  = fmaxf(Q / cnt - mean * mean, 0.f);
    g_stats[b * 128 + t]      = mean;
    g_stats[b * 128 + 64 + t] = rsqrtf(var + 1e-5f);
}

// ---------------- Kernel 1c: normalize + sq (grid B*N/8, block 256) ----------------
__global__ __launch_bounds__(256) void knorm2(const float* __restrict__ emb,
                                              const int* __restrict__ nb, int N)
{
    const int t = threadIdx.x, w = t >> 5, lane = t & 31;
    const int row = blockIdx.x * 8 + w;
    const int b = row / N, i = row - b * N;

    const float m0 = g_stats[b * 128 + lane];
    const float m1 = g_stats[b * 128 + lane + 32];
    const float r0 = g_stats[b * 128 + 64 + lane];
    const float r1 = g_stats[b * 128 + 64 + lane + 32];

    const float* E = emb + (size_t)row * 64;
    float e0 = E[lane], e1 = E[lane + 32];
    float m = (i < nb[b]) ? 1.f : 0.f;
    g_embn[(size_t)row * 64 + lane]      = (e0 - m0) * r0 * m;
    g_embn[(size_t)row * 64 + lane + 32] = (e1 - m1) * r1 * m;

    float sq = e0 * e0 + e1 * e1;
    #pragma unroll
    for (int o = 16; o; o >>= 1) sq += __shfl_down_sync(0xffffffffu, sq, o);
    if (lane == 0) g_sq[row] = sq;
}

// ---------------- Kernel 2: fused tensor-core Gram -> eltwise -> adj/deg -> SpMM ----------------
#define SEJ 68
#define SEN 72
#define SSS 68

__global__ __launch_bounds__(256, 2) void kadj(
    const float* __restrict__ emb, const float* __restrict__ adj_in,
    const int* __restrict__ nb, const float* __restrict__ sigma_p,
    const float* __restrict__ cw, float* __restrict__ adj_out, int N)
{
    extern __shared__ float sm[];
    float* sEj = sm;                                   // [2][64][SEJ] raw fp32 bits
    float* sEn = sm + 2 * 64 * SEJ;                    // [2][64][SEN]
    uint32_t* sS = (uint32_t*)(sm + 2 * 64 * (SEJ + SEN)); // [64][SSS] tf32
    float* ssqj = sm + 2 * 64 * (SEJ + SEN) + 64 * SSS;    // [2][64]
    float* sdeg = ssqj + 128;                          // [64]

    const int b = blockIdx.y;
    const int ibase = blockIdx.x * 64;
    const int t = threadIdx.x;
    const int w = t >> 5, lane = t & 31;
    const int rowb = (w >> 1) * 16, colb = (w & 1) * 32;
    const int g = lane >> 2, tg = lane & 3;

    const float inv_sigma = 1.0f / sigma_p[0];
    const float w0 = cw[0], w1 = cw[1];
    const int nbv = nb[b];

    const float* E    = emb     + (size_t)b * N * 64;
    const float* En   = g_embn  + (size_t)b * N * 64;
    const float* SQ   = g_sq    + b * N;
    const float* Ain  = adj_in  + (size_t)b * N * N;
    float*       Aout = adj_out + (size_t)b * N * N;

    const uint32_t u_sEj  = (uint32_t)__cvta_generic_to_shared(sEj);
    const uint32_t u_sEn  = (uint32_t)__cvta_generic_to_shared(sEn);
    const uint32_t u_ssqj = (uint32_t)__cvta_generic_to_shared(ssqj);

    const int gi0 = ibase + rowb + g;
    const int gi1 = gi0 + 8;

    // ---- stage helper (cp.async, raw fp32): 64 rows x 16 chunks per array ----
    auto stage = [&](int pb, int jt) {
        const uint32_t bEj = u_sEj + (uint32_t)(pb * 64 * SEJ) * 4u;
        const uint32_t bEn = u_sEn + (uint32_t)(pb * 64 * SEN) * 4u;
        #pragma unroll
        for (int k = 0; k < 4; k++) {                 // FIX: 4x256 = 1024 chunks (was 2)
            const int idx = t + k * 256;
            const int j = idx >> 4, f4 = (idx & 15) << 2;
            cpa16(bEj + (uint32_t)(j * SEJ + f4) * 4u, &E[(size_t)(jt + j) * 64 + f4]);
            cpa16(bEn + (uint32_t)(j * SEN + f4) * 4u, &En[(size_t)(jt + j) * 64 + f4]);
        }
        if (t < 16)
            cpa16(u_ssqj + (uint32_t)(pb * 64 + t * 4) * 4u, &SQ[jt + t * 4]);
    };

    // prologue: stage tile 0, overlap with A-fragment loads
    stage(0, 0);
    asm volatile("cp.async.commit_group;\n");

    uint32_t aF[8][4];
    #pragma unroll
    for (int ks = 0; ks < 8; ks++) {
        aF[ks][0] = f2tf(E[(size_t)gi0 * 64 + ks * 8 + tg]);
        aF[ks][1] = f2tf(E[(size_t)gi1 * 64 + ks * 8 + tg]);
        aF[ks][2] = f2tf(E[(size_t)gi0 * 64 + ks * 8 + tg + 4]);
        aF[ks][3] = f2tf(E[(size_t)gi1 * 64 + ks * 8 + tg + 4]);
    }
    const float sqi0 = SQ[gi0];
    const float sqi1 = SQ[gi1];
    if (t < 64) sdeg[t] = 0.f;
    const float mi0 = (gi0 < nbv) ? 1.f : 0.f;
    const float mi1 = (gi1 < nbv) ? 1.f : 0.f;

    float opa[4][4];
    #pragma unroll
    for (int n = 0; n < 4; n++)
        #pragma unroll
        for (int k = 0; k < 4; k++) opa[n][k] = 0.f;
    float dg0 = 0.f, dg1 = 0.f;

    asm volatile("cp.async.wait_group 0;\n");
    __syncthreads();

    int pb = 0;
    for (int jt = 0; jt < N; jt += 64, pb ^= 1) {
        // issue next tile's staging (hides under gemm1 + eltwise + gemm2)
        if (jt + 64 < N) stage(pb ^ 1, jt + 64);
        asm volatile("cp.async.commit_group;\n");

        // prefetch adj_in for this tile
        float2 a01[4], a23[4];
        #pragma unroll
        for (int nt = 0; nt < 4; nt++) {
            const int gj = jt + colb + nt * 8 + 2 * tg;
            a01[nt] = *(const float2*)&Ain[(size_t)gi0 * N + gj];
            a23[nt] = *(const float2*)&Ain[(size_t)gi1 * N + gj];
        }

        const uint32_t* Ej  = (const uint32_t*)(sEj + pb * 64 * SEJ);
        const uint32_t* EnS = (const uint32_t*)(sEn + pb * 64 * SEN);
        const float*    sqj = ssqj + pb * 64;

        // ---- gemm1: S = emb_i . emb_j^T ----
        float S[4][4];
        #pragma unroll
        for (int n = 0; n < 4; n++)
            #pragma unroll
            for (int k = 0; k < 4; k++) S[n][k] = 0.f;

        #pragma unroll
        for (int nt = 0; nt < 4; nt++) {
            const int n = colb + nt * 8;
            #pragma unroll
            for (int ks = 0; ks < 8; ks++) {
                uint32_t b0 = Ej[(n + g) * SEJ + ks * 8 + tg];
                uint32_t b1 = Ej[(n + g) * SEJ + ks * 8 + tg + 4];
                MMA_TF32(S[nt], aF[ks][0], aF[ks][1], aF[ks][2], aF[ks][3], b0, b1);
            }
        }

        // ---- eltwise ----
        #pragma unroll
        for (int nt = 0; nt < 4; nt++) {
            const int jl = colb + nt * 8 + 2 * tg;
            const int gj = jt + jl;
            const float sqj0 = sqj[jl], sqj1 = sqj[jl + 1];
            const float mj0 = (gj     < nbv) ? 1.f : 0.f;
            const float mj1 = (gj + 1 < nbv) ? 1.f : 0.f;

            float v00 = (w0 * a01[nt].x + w1 * __expf(-fmaxf(sqi0 + sqj0 - 2.f * S[nt][0], 0.f) * inv_sigma)) * (mi0 * mj0);
            float v01 = (w0 * a01[nt].y + w1 * __expf(-fmaxf(sqi0 + sqj1 - 2.f * S[nt][1], 0.f) * inv_sigma)) * (mi0 * mj1);
            float v10 = (w0 * a23[nt].x + w1 * __expf(-fmaxf(sqi1 + sqj0 - 2.f * S[nt][2], 0.f) * inv_sigma)) * (mi1 * mj0);
            float v11 = (w0 * a23[nt].y + w1 * __expf(-fmaxf(sqi1 + sqj1 - 2.f * S[nt][3], 0.f) * inv_sigma)) * (mi1 * mj1);

            dg0 += v00 + v01;
            dg1 += v10 + v11;

            *(float2*)&Aout[(size_t)gi0 * N + gj] = make_float2(v00, v01);
            *(float2*)&Aout[(size_t)gi1 * N + gj] = make_float2(v10, v11);

            const int il0 = rowb + g;
            sS[il0 * SSS + jl]           = f2tf(v00);
            sS[il0 * SSS + jl + 1]       = f2tf(v01);
            sS[(il0 + 8) * SSS + jl]     = f2tf(v10);
            sS[(il0 + 8) * SSS + jl + 1] = f2tf(v11);
        }
        __syncthreads();

        // ---- gemm2: op_adj += adj_tile @ embn_j ----
        #pragma unroll
        for (int ks = 0; ks < 8; ks++) {
            uint32_t A0 = sS[(rowb + g)     * SSS + ks * 8 + tg];
            uint32_t A1 = sS[(rowb + g + 8) * SSS + ks * 8 + tg];
            uint32_t A2 = sS[(rowb + g)     * SSS + ks * 8 + tg + 4];
            uint32_t A3 = sS[(rowb + g + 8) * SSS + ks * 8 + tg + 4];
            #pragma unroll
            for (int nt = 0; nt < 4; nt++) {
                const int nf = colb + nt * 8;
                uint32_t B0 = EnS[(ks * 8 + tg)     * SEN + nf + g];
                uint32_t B1 = EnS[(ks * 8 + tg + 4) * SEN + nf + g];
                MMA_TF32(opa[nt], A0, A1, A2, A3, B0, B1);
            }
        }

        asm volatile("cp.async.wait_group 0;\n");
        __syncthreads();
    }

    // ---- epilogue ----
    dg0 += __shfl_xor_sync(0xffffffffu, dg0, 1);
    dg0 += __shfl_xor_sync(0xffffffffu, dg0, 2);
    dg1 += __shfl_xor_sync(0xffffffffu, dg1, 1);
    dg1 += __shfl_xor_sync(0xffffffffu, dg1, 2);
    if (tg == 0) {
        atomicAdd(&sdeg[rowb + g], dg0);
        atomicAdd(&sdeg[rowb + g + 8], dg1);
    }
    __syncthreads();
    if (t < 64) g_deg[b * N + ibase + t] = sdeg[t];

    #pragma unroll
    for (int nt = 0; nt < 4; nt++) {
        const int f0 = colb + nt * 8 + 2 * tg;
        *(float2*)&g_opadj[(size_t)(b * N + gi0) * 64 + f0] = make_float2(opa[nt][0], opa[nt][1]);
        *(float2*)&g_opadj[(size_t)(b * N + gi1) * 64 + f0] = make_float2(opa[nt][2], opa[nt][3]);
    }
}

// ---------------- Kernel 3: fused 2-stage MLP, one warp per node ----------------
__global__ __launch_bounds__(256, 2) void knn(
    const float* __restrict__ embn, const float* __restrict__ opadj,
    const float* __restrict__ deg,  const float* __restrict__ emb_in,
    const float* __restrict__ W1,   const float* __restrict__ b1,
    const float* __restrict__ W2,   const float* __restrict__ b2,
    float* __restrict__ out)
{
    extern __shared__ float smn[];
    float* sW1 = smn;
    float* sW2 = sW1 + 128 * 64;
    float* sb1 = sW2 + 128 * 64;
    float* sb2 = sb1 + 64;
    float* sx  = sb2 + 64;

    const int t = threadIdx.x;
    const int w = t >> 5, lane = t & 31;

    for (int idx = t; idx < 2048; idx += 256) {
        *(float4*)&sW1[idx * 4] = *(const float4*)&W1[idx * 4];
        *(float4*)&sW2[idx * 4] = *(const float4*)&W2[idx * 4];
    }
    if (t < 64) { sb1[t] = b1[t]; sb2[t] = b2[t]; }
    __syncthreads();

    float* x = sx + w * 132;
    const int node0 = blockIdx.x * 64 + w * 8;

    for (int it = 0; it < 8; it++) {
        const int gn = node0 + it;
        const float dg = deg[gn];

        x[lane]      = dg * embn[(size_t)gn * 64 + lane];
        x[lane + 32] = dg * embn[(size_t)gn * 64 + lane + 32];
        x[lane + 64] = opadj[(size_t)gn * 64 + lane];
        x[lane + 96] = opadj[(size_t)gn * 64 + lane + 32];
        __syncwarp();

        float acc0 = sb1[2 * lane], acc1 = sb1[2 * lane + 1];
        #pragma unroll 8
        for (int k = 0; k < 128; k += 4) {
            float4 xv = *(const float4*)&x[k];
            float2 w0v = *(const float2*)&sW1[(k + 0) * 64 + 2 * lane];
            float2 w1v = *(const float2*)&sW1[(k + 1) * 64 + 2 * lane];
            float2 w2v = *(const float2*)&sW1[(k + 2) * 64 + 2 * lane];
            float2 w3v = *(const float2*)&sW1[(k + 3) * 64 + 2 * lane];
            acc0 += xv.x * w0v.x + xv.y * w1v.x + xv.z * w2v.x + xv.w * w3v.x;
            acc1 += xv.x * w0v.y + xv.y * w1v.y + xv.z * w2v.y + xv.w * w3v.y;
        }
        __syncwarp();

        x[lane]          = emb_in[(size_t)gn * 64 + lane];
        x[lane + 32]     = emb_in[(size_t)gn * 64 + lane + 32];
        x[64 + 2 * lane]     = acc0;
        x[64 + 2 * lane + 1] = acc1;
        __syncwarp();

        float o0 = sb2[2 * lane], o1 = sb2[2 * lane + 1];
        #pragma unroll 8
        for (int k = 0; k < 128; k += 4) {
            float4 xv = *(const float4*)&x[k];
            float2 w0v = *(const float2*)&sW2[(k + 0) * 64 + 2 * lane];
            float2 w1v = *(const float2*)&sW2[(k + 1) * 64 + 2 * lane];
            float2 w2v = *(const float2*)&sW2[(k + 2) * 64 + 2 * lane];
            float2 w3v = *(const float2*)&sW2[(k + 3) * 64 + 2 * lane];
            o0 += xv.x * w0v.x + xv.y * w1v.x + xv.z * w2v.x + xv.w * w3v.x;
            o1 += xv.x * w0v.y + xv.y * w1v.y + xv.z * w2v.y + xv.w * w3v.y;
        }
        o0 = fmaxf(o0, 0.f);
        o1 = fmaxf(o1, 0.f);
        *(float2*)&out[(size_t)gn * 64 + 2 * lane] = make_float2(o0, o1);
        __syncwarp();
    }
}

// ---------------- launch ----------------
extern "C" void kernel_launch(void* const* d_in, const int* in_sizes, int n_in,
                              void* d_out, int out_size)
{
    const float* emb_in = (const float*)d_in[0];
    const float* adj_in = (const float*)d_in[1];
    // d_in[2] adj_mask: unused (recomputed from batch_nb_nodes)
    const int*   nb     = (const int*)d_in[3];
    const float* sigma  = (const float*)d_in[4];
    const float* cw     = (const float*)d_in[5];
    const float* convW  = (const float*)d_in[6];
    const float* convb  = (const float*)d_in[7];
    const float* nuW    = (const float*)d_in[8];
    const float* nub    = (const float*)d_in[9];

    const int B = in_sizes[3];
    const int N = in_sizes[0] / (B * 64);

    float* out_emb = (float*)d_out;                    // (B,N,64)
    float* out_adj = out_emb + (size_t)B * N * 64;     // (B,N,N)

    float *p_embn, *p_opadj, *p_deg;
    cudaGetSymbolAddress((void**)&p_embn,  g_embn);
    cudaGetSymbolAddress((void**)&p_opadj, g_opadj);
    cudaGetSymbolAddress((void**)&p_deg,   g_deg);

    kstat1<<<dim3(B, 8), 256>>>(emb_in, N);
    kstat2<<<B, 64>>>(nb);
    knorm2<<<(B * N) / 8, 256>>>(emb_in, nb, N);

    const size_t smemAdj = (size_t)(2 * 64 * (SEJ + SEN) + 64 * SSS + 128 + 64) * sizeof(float);
    cudaFuncSetAttribute(kadj, cudaFuncAttributeMaxDynamicSharedMemorySize, (int)smemAdj);
    kadj<<<dim3(N / 64, B), 256, smemAdj>>>(emb_in, adj_in, nb, sigma, cw, out_adj, N);

    const size_t smemNN = (size_t)(2 * 128 * 64 + 128 + 8 * 132) * sizeof(float);
    cudaFuncSetAttribute(knn, cudaFuncAttributeMaxDynamicSharedMemorySize, (int)smemNN);
    knn<<<(B * N) / 64, 256, smemNN>>>(p_embn, p_opadj, p_deg, emb_in,
                                       convW, convb, nuW, nub, out_emb);
}

// round 6
// speedup vs baseline: 2.8049x; 1.0696x over previous
#include <cuda_runtime.h>
#include <cstdint>

#define MAXB 8
#define MAXN 2048

// ---------------- scratch ----------------
__device__ float g_embnP[MAXB * MAXN * 64];   // emb_n, phi-permuted features
__device__ float g_Ep   [MAXB * MAXN * 64];   // emb,   phi-permuted features
__device__ float g_sq   [MAXB * MAXN];
__device__ float g_deg  [MAXB * MAXN];
__device__ float g_opadjP[MAXB * MAXN * 64];  // op_adj, phi-permuted features
__device__ float g_part [MAXB * 8 * 128];
__device__ float g_stats[MAXB * 128];

// phi: within each 8-block, slot r stored at ((r&3)<<1)|(r>>2)  (maps (tg,tg+4)->adjacent)
__device__ __forceinline__ int phi(int k) {
    int r = k & 7;
    return (k & ~7) | (((r & 3) << 1) | (r >> 2));
}

__device__ __forceinline__ uint32_t f2tf(float x) {
    uint32_t r;
    asm("cvt.rna.tf32.f32 %0, %1;" : "=r"(r) : "f"(x));
    return r;
}

// split: v ~= hi + lo (both tf32, RNA) -> near-fp32 via 3 MMAs
__device__ __forceinline__ void split_tf(float v, uint32_t& hi, uint32_t& lo) {
    hi = f2tf(v);
    lo = f2tf(v - __uint_as_float(hi));
}

__device__ __forceinline__ void cpa16(uint32_t saddr, const void* gaddr) {
    asm volatile("cp.async.cg.shared.global [%0], [%1], 16;\n"
                 :: "r"(saddr), "l"(gaddr));
}

#define MMA_TF32(d, a0, a1, a2, a3, b0, b1)                                  \
    asm volatile(                                                            \
        "mma.sync.aligned.m16n8k8.row.col.f32.tf32.tf32.f32 "                \
        "{%0,%1,%2,%3}, {%4,%5,%6,%7}, {%8,%9}, {%0,%1,%2,%3};\n"            \
        : "+f"(d[0]), "+f"(d[1]), "+f"(d[2]), "+f"(d[3])                     \
        : "r"(a0), "r"(a1), "r"(a2), "r"(a3), "r"(b0), "r"(b1))

// ---------------- Kernel 1a: partial sums (grid B x 8) ----------------
__global__ __launch_bounds__(256) void kstat1(const float* __restrict__ emb, int N)
{
    __shared__ float ssum[4][64], ssq[4][64];
    const int b = blockIdx.x, slice = blockIdx.y;
    const int t = threadIdx.x, f = t & 63, g = t >> 6;
    const int r0 = slice * (N / 8), r1 = r0 + N / 8;
    const float* E = emb + (size_t)b * N * 64;

    float s = 0.f, q = 0.f;
    for (int i = r0 + g; i < r1; i += 4) {
        float v = E[(size_t)i * 64 + f];
        s += v; q += v * v;
    }
    ssum[g][f] = s; ssq[g][f] = q;
    __syncthreads();
    if (t < 64) {
        g_part[(b * 8 + slice) * 128 + t]      = ssum[0][t] + ssum[1][t] + ssum[2][t] + ssum[3][t];
        g_part[(b * 8 + slice) * 128 + 64 + t] = ssq[0][t]  + ssq[1][t]  + ssq[2][t]  + ssq[3][t];
    }
}

// ---------------- Kernel 1b: finish stats ----------------
__global__ __launch_bounds__(64) void kstat2(const int* __restrict__ nb)
{
    const int b = blockIdx.x, t = threadIdx.x;
    float S = 0.f, Q = 0.f;
    #pragma unroll
    for (int s = 0; s < 8; s++) {
        S += g_part[(b * 8 + s) * 128 + t];
        Q += g_part[(b * 8 + s) * 128 + 64 + t];
    }
    float cnt  = fmaxf((float)nb[b], 1.f);
    float mean = S / cnt;
    float var  = fmaxf(Q / cnt - mean * mean, 0.f);
    g_stats[b * 128 + t]      = mean;
    g_stats[b * 128 + 64 + t] = rsqrtf(var + 1e-5f);
}

// ---------------- Kernel 1c: normalize + permuted copies + sq ----------------
__global__ __launch_bounds__(256) void knorm2(const float* __restrict__ emb,
                                              const int* __restrict__ nb, int N)
{
    const int t = threadIdx.x, w = t >> 5, lane = t & 31;
    const int row = blockIdx.x * 8 + w;
    const int b = row / N, i = row - b * N;

    const float m0 = g_stats[b * 128 + lane];
    const float m1 = g_stats[b * 128 + lane + 32];
    const float r0 = g_stats[b * 128 + 64 + lane];
    const float r1 = g_stats[b * 128 + 64 + lane + 32];

    const float* E = emb + (size_t)row * 64;
    float e0 = E[lane], e1 = E[lane + 32];
    float m = (i < nb[b]) ? 1.f : 0.f;

    const int pf0 = phi(lane), pf1 = phi(lane + 32);
    g_Ep   [(size_t)row * 64 + pf0] = e0;
    g_Ep   [(size_t)row * 64 + pf1] = e1;
    g_embnP[(size_t)row * 64 + pf0] = (e0 - m0) * r0 * m;
    g_embnP[(size_t)row * 64 + pf1] = (e1 - m1) * r1 * m;

    float sq = e0 * e0 + e1 * e1;
    #pragma unroll
    for (int o = 16; o; o >>= 1) sq += __shfl_down_sync(0xffffffffu, sq, o);
    if (lane == 0) g_sq[row] = sq;
}

// ---------------- Kernel 2: fused Gram -> eltwise -> adj/deg -> SpMM ----------------
#define SEJ 72
#define SSS 72

__global__ __launch_bounds__(256, 2) void kadj(
    const float* __restrict__ adj_in,
    const int* __restrict__ nb, const float* __restrict__ sigma_p,
    const float* __restrict__ cw, float* __restrict__ adj_out, int N)
{
    extern __shared__ float sm[];
    float*    sEj  = sm;                         // [2][64][SEJ] raw fp32, phi-permuted f
    uint32_t* sS   = (uint32_t*)(sm + 2 * 64 * SEJ);  // [64][SSS] adj tile (tf32), phi-permuted j
    float*    ssqj = sm + 2 * 64 * SEJ + 64 * SSS;    // [2][64]
    float*    sdeg = ssqj + 128;                 // [64]

    const int b = blockIdx.y;
    const int ibase = blockIdx.x * 64;
    const int t = threadIdx.x;
    const int w = t >> 5, lane = t & 31;
    const int rowb = (w >> 1) * 16, colb = (w & 1) * 32;
    const int g = lane >> 2, tg = lane & 3;
    const int phig = ((g & 3) << 1) | (g >> 2);          // phi within 8-block of g
    const int p0 = (((2 * tg) & 3) << 1) | ((2 * tg) >> 2);
    const int p1 = (((2 * tg + 1) & 3) << 1) | ((2 * tg + 1) >> 2);

    const float inv_sigma = 1.0f / sigma_p[0];
    const float w0 = cw[0], w1 = cw[1];
    const int nbv = nb[b];

    const float* Ep   = g_Ep    + (size_t)b * N * 64;
    const float* SQ   = g_sq    + b * N;
    const float* Ain  = adj_in  + (size_t)b * N * N;
    float*       Aout = adj_out + (size_t)b * N * N;

    const uint32_t u_sEj  = (uint32_t)__cvta_generic_to_shared(sEj);
    const uint32_t u_ssqj = (uint32_t)__cvta_generic_to_shared(ssqj);

    const int gi0 = ibase + rowb + g;
    const int gi1 = gi0 + 8;

    auto stage = [&](int pb, int jt) {
        const uint32_t bEj = u_sEj + (uint32_t)(pb * 64 * SEJ) * 4u;
        #pragma unroll
        for (int k = 0; k < 4; k++) {
            const int idx = t + k * 256;
            const int j = idx >> 4, f4 = (idx & 15) << 2;
            cpa16(bEj + (uint32_t)(j * SEJ + f4) * 4u, &Ep[(size_t)(jt + j) * 64 + f4]);
        }
        if (t < 16)
            cpa16(u_ssqj + (uint32_t)(pb * 64 + t * 4) * 4u, &SQ[jt + t * 4]);
    };

    stage(0, 0);
    asm volatile("cp.async.commit_group;\n");

    // A fragments (RNA tf32), phi-adjacent pairs -> float2 loads
    uint32_t aF[8][4];
    #pragma unroll
    for (int ks = 0; ks < 8; ks++) {
        float2 q0 = *(const float2*)&Ep[(size_t)gi0 * 64 + ks * 8 + 2 * tg];
        float2 q1 = *(const float2*)&Ep[(size_t)gi1 * 64 + ks * 8 + 2 * tg];
        aF[ks][0] = f2tf(q0.x);
        aF[ks][1] = f2tf(q1.x);
        aF[ks][2] = f2tf(q0.y);
        aF[ks][3] = f2tf(q1.y);
    }
    const float sqi0 = SQ[gi0];
    const float sqi1 = SQ[gi1];
    if (t < 64) sdeg[t] = 0.f;
    const float mi0 = (gi0 < nbv) ? 1.f : 0.f;
    const float mi1 = (gi1 < nbv) ? 1.f : 0.f;

    // layernorm params for gemm2-B on-the-fly: f = colb + nt*8 + g (fixed per nt)
    float rs[4], mr[4];
    int nfg[4];
    #pragma unroll
    for (int nt = 0; nt < 4; nt++) {
        const int f = colb + nt * 8 + g;
        const float mean = g_stats[b * 128 + f];
        const float rstd = g_stats[b * 128 + 64 + f];
        rs[nt] = rstd;
        mr[nt] = mean * rstd;
        nfg[nt] = colb + nt * 8 + phig;
    }

    float opa[4][4];
    #pragma unroll
    for (int n = 0; n < 4; n++)
        #pragma unroll
        for (int k = 0; k < 4; k++) opa[n][k] = 0.f;
    float dg0 = 0.f, dg1 = 0.f;

    asm volatile("cp.async.wait_group 0;\n");
    __syncthreads();

    int pb = 0;
    for (int jt = 0; jt < N; jt += 64, pb ^= 1) {
        if (jt + 64 < N) stage(pb ^ 1, jt + 64);
        asm volatile("cp.async.commit_group;\n");

        // prefetch adj_in
        float2 a01[4], a23[4];
        #pragma unroll
        for (int nt = 0; nt < 4; nt++) {
            const int gj = jt + colb + nt * 8 + 2 * tg;
            a01[nt] = *(const float2*)&Ain[(size_t)gi0 * N + gj];
            a23[nt] = *(const float2*)&Ain[(size_t)gi1 * N + gj];
        }

        const float*    EjF = sEj + pb * 64 * SEJ;
        const uint32_t* Ej  = (const uint32_t*)EjF;
        const float*    sqj = ssqj + pb * 64;

        // ---- gemm1: S = emb_i . emb_j^T  (B pairs via LDS.64) ----
        float S[4][4];
        #pragma unroll
        for (int n = 0; n < 4; n++)
            #pragma unroll
            for (int k = 0; k < 4; k++) S[n][k] = 0.f;

        #pragma unroll
        for (int nt = 0; nt < 4; nt++) {
            const int n = colb + nt * 8;
            #pragma unroll
            for (int ks = 0; ks < 8; ks++) {
                uint2 bv = *(const uint2*)&Ej[(n + g) * SEJ + ks * 8 + 2 * tg];
                MMA_TF32(S[nt], aF[ks][0], aF[ks][1], aF[ks][2], aF[ks][3], bv.x, bv.y);
            }
        }

        // ---- eltwise: RBF, combine, mask; write adj; stash S tile (RNA tf32, phi cols) ----
        #pragma unroll
        for (int nt = 0; nt < 4; nt++) {
            const int jl = colb + nt * 8 + 2 * tg;
            const int gj = jt + jl;
            const float sqj0 = sqj[jl], sqj1 = sqj[jl + 1];
            const float mj0 = (gj     < nbv) ? 1.f : 0.f;
            const float mj1 = (gj + 1 < nbv) ? 1.f : 0.f;

            float v00 = (w0 * a01[nt].x + w1 * __expf(-fmaxf(sqi0 + sqj0 - 2.f * S[nt][0], 0.f) * inv_sigma)) * (mi0 * mj0);
            float v01 = (w0 * a01[nt].y + w1 * __expf(-fmaxf(sqi0 + sqj1 - 2.f * S[nt][1], 0.f) * inv_sigma)) * (mi0 * mj1);
            float v10 = (w0 * a23[nt].x + w1 * __expf(-fmaxf(sqi1 + sqj0 - 2.f * S[nt][2], 0.f) * inv_sigma)) * (mi1 * mj0);
            float v11 = (w0 * a23[nt].y + w1 * __expf(-fmaxf(sqi1 + sqj1 - 2.f * S[nt][3], 0.f) * inv_sigma)) * (mi1 * mj1);

            dg0 += v00 + v01;
            dg1 += v10 + v11;

            *(float2*)&Aout[(size_t)gi0 * N + gj] = make_float2(v00, v01);
            *(float2*)&Aout[(size_t)gi1 * N + gj] = make_float2(v10, v11);

            const int cb = colb + nt * 8;
            sS[(rowb + g)     * SSS + cb + p0] = f2tf(v00);
            sS[(rowb + g)     * SSS + cb + p1] = f2tf(v01);
            sS[(rowb + g + 8) * SSS + cb + p0] = f2tf(v10);
            sS[(rowb + g + 8) * SSS + cb + p1] = f2tf(v11);
        }
        // pairwise barrier: only warps (w, w^1) share sS rows
        asm volatile("bar.sync %0, 64;" :: "r"(1 + (w >> 1)) : "memory");

        // ---- gemm2: op_adj += adj_tile @ En(on-the-fly, RNA, from sEj) ----
        #pragma unroll
        for (int ks = 0; ks < 8; ks++) {
            uint2 A02 = *(const uint2*)&sS[(rowb + g)     * SSS + ks * 8 + 2 * tg];
            uint2 A13 = *(const uint2*)&sS[(rowb + g + 8) * SSS + ks * 8 + 2 * tg];
            const int j0 = jt + ks * 8 + tg;
            const bool m0 = j0 < nbv;
            const bool m1 = (j0 + 4) < nbv;
            const int r0o = (ks * 8 + tg) * SEJ;
            const int r1o = (ks * 8 + tg + 4) * SEJ;
            #pragma unroll
            for (int nt = 0; nt < 4; nt++) {
                float e0 = EjF[r0o + nfg[nt]];
                float e1 = EjF[r1o + nfg[nt]];
                uint32_t B0 = m0 ? f2tf(fmaf(e0, rs[nt], -mr[nt])) : 0u;
                uint32_t B1 = m1 ? f2tf(fmaf(e1, rs[nt], -mr[nt])) : 0u;
                MMA_TF32(opa[nt], A02.x, A13.x, A02.y, A13.y, B0, B1);
            }
        }

        asm volatile("cp.async.wait_group 0;\n");
        __syncthreads();
    }

    // ---- epilogue ----
    dg0 += __shfl_xor_sync(0xffffffffu, dg0, 1);
    dg0 += __shfl_xor_sync(0xffffffffu, dg0, 2);
    dg1 += __shfl_xor_sync(0xffffffffu, dg1, 1);
    dg1 += __shfl_xor_sync(0xffffffffu, dg1, 2);
    if (tg == 0) {
        atomicAdd(&sdeg[rowb + g], dg0);
        atomicAdd(&sdeg[rowb + g + 8], dg1);
    }
    __syncthreads();
    if (t < 64) g_deg[b * N + ibase + t] = sdeg[t];

    // op_adj written phi-permuted (knn consumes permuted layout)
    #pragma unroll
    for (int nt = 0; nt < 4; nt++) {
        const int cb = colb + nt * 8;
        g_opadjP[(size_t)(b * N + gi0) * 64 + cb + p0] = opa[nt][0];
        g_opadjP[(size_t)(b * N + gi0) * 64 + cb + p1] = opa[nt][1];
        g_opadjP[(size_t)(b * N + gi1) * 64 + cb + p0] = opa[nt][2];
        g_opadjP[(size_t)(b * N + gi1) * 64 + cb + p1] = opa[nt][3];
    }
}

// ---------------- Kernel 3: fused 2-stage MLP, split-tf32 MMA (near-fp32) ----------------
#define SWP 136
#define SX  136

__global__ __launch_bounds__(256, 1) void knn(
    const float* __restrict__ embnP, const float* __restrict__ opadjP,
    const float* __restrict__ deg,   const float* __restrict__ Ep,
    const float* __restrict__ W1,    const float* __restrict__ b1,
    const float* __restrict__ W2,    const float* __restrict__ b2,
    float* __restrict__ out)
{
    extern __shared__ float smn[];
    uint32_t* sW1h = (uint32_t*)smn;            // [64][SWP]  W1^T hi (tf32), phi cols
    uint32_t* sW1l = sW1h + 64 * SWP;           // [64][SWP]  W1^T lo
    uint32_t* sW2h = sW1l + 64 * SWP;
    uint32_t* sW2l = sW2h + 64 * SWP;
    float*    sx   = (float*)(sW2l + 64 * SWP); // [128][SX]  x fp32, phi cols
    float*    sb1  = sx + 128 * SX;             // [64]
    float*    sb2  = sb1 + 64;                  // [64]

    const int t = threadIdx.x;
    const int w = t >> 5, lane = t & 31;
    const int g = lane >> 2, tg = lane & 3;
    const int r0 = w * 16;
    const int node0 = blockIdx.x * 128;
    const int p0 = (((2 * tg) & 3) << 1) | ((2 * tg) >> 2);
    const int p1 = (((2 * tg + 1) & 3) << 1) | ((2 * tg + 1) >> 2);

    // stage weights (transposed, phi cols, pre-split hi/lo) + biases
    for (int idx = t; idx < 8192; idx += 256) {
        const int k = idx >> 6, n = idx & 63;
        const int pk = phi(k);
        uint32_t h, l;
        split_tf(W1[idx], h, l);
        sW1h[n * SWP + pk] = h; sW1l[n * SWP + pk] = l;
        split_tf(W2[idx], h, l);
        sW2h[n * SWP + pk] = h; sW2l[n * SWP + pk] = l;
    }
    if (t < 64) { sb1[t] = b1[t]; sb2[t] = b2[t]; }

    // stage x1 = [deg*embn (phi), opadj (phi)]
    for (int idx = t; idx < 2048; idx += 256) {
        const int node = idx >> 4, c = (idx & 15) << 2;
        const float dgv = deg[node0 + node];
        float4 v = *(const float4*)&embnP[(size_t)(node0 + node) * 64 + c];
        v.x *= dgv; v.y *= dgv; v.z *= dgv; v.w *= dgv;
        *(float4*)&sx[node * SX + c] = v;
        *(float4*)&sx[node * SX + 64 + c] =
            *(const float4*)&opadjP[(size_t)(node0 + node) * 64 + c];
    }
    __syncthreads();

    // ---- stage 1: upd = x1 @ W1  (split: hh + lh + hl) ----
    float acc1[8][4];
    #pragma unroll
    for (int n = 0; n < 8; n++)
        #pragma unroll
        for (int k = 0; k < 4; k++) acc1[n][k] = 0.f;

    #pragma unroll
    for (int ks = 0; ks < 16; ks++) {
        float2 A0 = *(const float2*)&sx[(r0 + g)     * SX + ks * 8 + 2 * tg];
        float2 A1 = *(const float2*)&sx[(r0 + g + 8) * SX + ks * 8 + 2 * tg];
        uint32_t ah[4], al[4];
        split_tf(A0.x, ah[0], al[0]);
        split_tf(A1.x, ah[1], al[1]);
        split_tf(A0.y, ah[2], al[2]);
        split_tf(A1.y, ah[3], al[3]);
        #pragma unroll
        for (int nt = 0; nt < 8; nt++) {
            uint2 bh = *(const uint2*)&sW1h[(nt * 8 + g) * SWP + ks * 8 + 2 * tg];
            uint2 bl = *(const uint2*)&sW1l[(nt * 8 + g) * SWP + ks * 8 + 2 * tg];
            MMA_TF32(acc1[nt], ah[0], ah[1], ah[2], ah[3], bh.x, bh.y);
            MMA_TF32(acc1[nt], al[0], al[1], al[2], al[3], bh.x, bh.y);
            MMA_TF32(acc1[nt], ah[0], ah[1], ah[2], ah[3], bl.x, bl.y);
        }
    }
    __syncthreads();   // all warps done reading x1

    // build x2 = [emb_in (phi), upd+b1 (phi)]
    for (int idx = t; idx < 2048; idx += 256) {
        const int node = idx >> 4, c = (idx & 15) << 2;
        *(float4*)&sx[node * SX + c] = *(const float4*)&Ep[(size_t)(node0 + node) * 64 + c];
    }
    #pragma unroll
    for (int nt = 0; nt < 8; nt++) {
        const int f0 = nt * 8 + 2 * tg;
        const int base = 64 + nt * 8;
        sx[(r0 + g)     * SX + base + p0] = acc1[nt][0] + sb1[f0];
        sx[(r0 + g)     * SX + base + p1] = acc1[nt][1] + sb1[f0 + 1];
        sx[(r0 + g + 8) * SX + base + p0] = acc1[nt][2] + sb1[f0];
        sx[(r0 + g + 8) * SX + base + p1] = acc1[nt][3] + sb1[f0 + 1];
    }
    __syncthreads();

    // ---- stage 2: out = relu(x2 @ W2 + b2)  (split) ----
    float acc2[8][4];
    #pragma unroll
    for (int n = 0; n < 8; n++)
        #pragma unroll
        for (int k = 0; k < 4; k++) acc2[n][k] = 0.f;

    #pragma unroll
    for (int ks = 0; ks < 16; ks++) {
        float2 A0 = *(const float2*)&sx[(r0 + g)     * SX + ks * 8 + 2 * tg];
        float2 A1 = *(const float2*)&sx[(r0 + g + 8) * SX + ks * 8 + 2 * tg];
        uint32_t ah[4], al[4];
        split_tf(A0.x, ah[0], al[0]);
        split_tf(A1.x, ah[1], al[1]);
        split_tf(A0.y, ah[2], al[2]);
        split_tf(A1.y, ah[3], al[3]);
        #pragma unroll
        for (int nt = 0; nt < 8; nt++) {
            uint2 bh = *(const uint2*)&sW2h[(nt * 8 + g) * SWP + ks * 8 + 2 * tg];
            uint2 bl = *(const uint2*)&sW2l[(nt * 8 + g) * SWP + ks * 8 + 2 * tg];
            MMA_TF32(acc2[nt], ah[0], ah[1], ah[2], ah[3], bh.x, bh.y);
            MMA_TF32(acc2[nt], al[0], al[1], al[2], al[3], bh.x, bh.y);
            MMA_TF32(acc2[nt], ah[0], ah[1], ah[2], ah[3], bl.x, bl.y);
        }
    }

    #pragma unroll
    for (int nt = 0; nt < 8; nt++) {
        const int f0 = nt * 8 + 2 * tg;
        float o00 = fmaxf(acc2[nt][0] + sb2[f0],     0.f);
        float o01 = fmaxf(acc2[nt][1] + sb2[f0 + 1], 0.f);
        float o10 = fmaxf(acc2[nt][2] + sb2[f0],     0.f);
        float o11 = fmaxf(acc2[nt][3] + sb2[f0 + 1], 0.f);
        *(float2*)&out[(size_t)(node0 + r0 + g)     * 64 + f0] = make_float2(o00, o01);
        *(float2*)&out[(size_t)(node0 + r0 + g + 8) * 64 + f0] = make_float2(o10, o11);
    }
}

// ---------------- launch ----------------
extern "C" void kernel_launch(void* const* d_in, const int* in_sizes, int n_in,
                              void* d_out, int out_size)
{
    const float* emb_in = (const float*)d_in[0];
    const float* adj_in = (const float*)d_in[1];
    // d_in[2] adj_mask: unused (recomputed from batch_nb_nodes)
    const int*   nb     = (const int*)d_in[3];
    const float* sigma  = (const float*)d_in[4];
    const float* cw     = (const float*)d_in[5];
    const float* convW  = (const float*)d_in[6];
    const float* convb  = (const float*)d_in[7];
    const float* nuW    = (const float*)d_in[8];
    const float* nub    = (const float*)d_in[9];

    const int B = in_sizes[3];
    const int N = in_sizes[0] / (B * 64);

    float* out_emb = (float*)d_out;                    // (B,N,64)
    float* out_adj = out_emb + (size_t)B * N * 64;     // (B,N,N)

    float *p_embnP, *p_opadjP, *p_deg, *p_Ep;
    cudaGetSymbolAddress((void**)&p_embnP,  g_embnP);
    cudaGetSymbolAddress((void**)&p_opadjP, g_opadjP);
    cudaGetSymbolAddress((void**)&p_deg,    g_deg);
    cudaGetSymbolAddress((void**)&p_Ep,     g_Ep);

    kstat1<<<dim3(B, 8), 256>>>(emb_in, N);
    kstat2<<<B, 64>>>(nb);
    knorm2<<<(B * N) / 8, 256>>>(emb_in, nb, N);

    const size_t smemAdj = (size_t)(2 * 64 * SEJ + 64 * SSS + 128 + 64) * sizeof(float);
    cudaFuncSetAttribute(kadj, cudaFuncAttributeMaxDynamicSharedMemorySize, (int)smemAdj);
    kadj<<<dim3(N / 64, B), 256, smemAdj>>>(adj_in, nb, sigma, cw, out_adj, N);

    const size_t smemNN = (size_t)(4 * 64 * SWP + 128 * SX + 128) * sizeof(float);
    cudaFuncSetAttribute(knn, cudaFuncAttributeMaxDynamicSharedMemorySize, (int)smemNN);
    knn<<<(B * N) / 128, 256, smemNN>>>(p_embnP, p_opadjP, p_deg, p_Ep,
                                        convW, convb, nuW, nub, out_emb);
}

// round 7
// speedup vs baseline: 3.0889x; 1.1013x over previous
#include <cuda_runtime.h>
#include <cstdint>

#define MAXB 8
#define MAXN 2048

// ---------------- scratch ----------------
__device__ float g_embnP[MAXB * MAXN * 64];   // emb_n, node-major, phi-permuted f (fp32, for knn)
__device__ float g_EnT  [MAXB * 64 * MAXN];   // emb_n^T [b][f][j], j phi-permuted, RNA-tf32 values
__device__ float g_Ep   [MAXB * MAXN * 64];   // emb,   node-major, phi-permuted f
__device__ float g_sq   [MAXB * MAXN];
__device__ float g_deg  [MAXB * MAXN];
__device__ float g_opadjP[MAXB * MAXN * 64];  // op_adj, node-major, phi-permuted f
__device__ float g_part [MAXB * 8 * 128];
__device__ float g_stats[MAXB * 128];

// phi: within each 8-block, slot r stored at ((r&3)<<1)|(r>>2)  (maps (tg,tg+4)->adjacent)
__device__ __forceinline__ int phi(int k) {
    int r = k & 7;
    return (k & ~7) | (((r & 3) << 1) | (r >> 2));
}

__device__ __forceinline__ uint32_t f2tf(float x) {
    uint32_t r;
    asm("cvt.rna.tf32.f32 %0, %1;" : "=r"(r) : "f"(x));
    return r;
}

// split: v ~= hi + lo (both tf32, RNA) -> near-fp32 via 3 MMAs
__device__ __forceinline__ void split_tf(float v, uint32_t& hi, uint32_t& lo) {
    hi = f2tf(v);
    lo = f2tf(v - __uint_as_float(hi));
}

__device__ __forceinline__ void cpa16(uint32_t saddr, const void* gaddr) {
    asm volatile("cp.async.cg.shared.global [%0], [%1], 16;\n"
                 :: "r"(saddr), "l"(gaddr));
}

#define MMA_TF32(d, a0, a1, a2, a3, b0, b1)                                  \
    asm volatile(                                                            \
        "mma.sync.aligned.m16n8k8.row.col.f32.tf32.tf32.f32 "                \
        "{%0,%1,%2,%3}, {%4,%5,%6,%7}, {%8,%9}, {%0,%1,%2,%3};\n"            \
        : "+f"(d[0]), "+f"(d[1]), "+f"(d[2]), "+f"(d[3])                     \
        : "r"(a0), "r"(a1), "r"(a2), "r"(a3), "r"(b0), "r"(b1))

// ---------------- Kernel 1a: partial sums (grid B x 8) ----------------
__global__ __launch_bounds__(256) void kstat1(const float* __restrict__ emb, int N)
{
    __shared__ float ssum[4][64], ssq[4][64];
    const int b = blockIdx.x, slice = blockIdx.y;
    const int t = threadIdx.x, f = t & 63, g = t >> 6;
    const int r0 = slice * (N / 8), r1 = r0 + N / 8;
    const float* E = emb + (size_t)b * N * 64;

    float s = 0.f, q = 0.f;
    for (int i = r0 + g; i < r1; i += 4) {
        float v = E[(size_t)i * 64 + f];
        s += v; q += v * v;
    }
    ssum[g][f] = s; ssq[g][f] = q;
    __syncthreads();
    if (t < 64) {
        g_part[(b * 8 + slice) * 128 + t]      = ssum[0][t] + ssum[1][t] + ssum[2][t] + ssum[3][t];
        g_part[(b * 8 + slice) * 128 + 64 + t] = ssq[0][t]  + ssq[1][t]  + ssq[2][t]  + ssq[3][t];
    }
}

// ---------------- Kernel 1b: finish stats ----------------
__global__ __launch_bounds__(64) void kstat2(const int* __restrict__ nb)
{
    const int b = blockIdx.x, t = threadIdx.x;
    float S = 0.f, Q = 0.f;
    #pragma unroll
    for (int s = 0; s < 8; s++) {
        S += g_part[(b * 8 + s) * 128 + t];
        Q += g_part[(b * 8 + s) * 128 + 64 + t];
    }
    float cnt  = fmaxf((float)nb[b], 1.f);
    float mean = S / cnt;
    float var  = fmaxf(Q / cnt - mean * mean, 0.f);
    g_stats[b * 128 + t]      = mean;
    g_stats[b * 128 + 64 + t] = rsqrtf(var + 1e-5f);
}

// ---------------- Kernel 1c: normalize + permuted/transposed copies + sq ----------------
__global__ __launch_bounds__(256) void knorm2(const float* __restrict__ emb,
                                              const int* __restrict__ nb, int N)
{
    __shared__ float stile[8][65];   // embn [j-local][f]

    const int t = threadIdx.x, w = t >> 5, lane = t & 31;
    const int row = blockIdx.x * 8 + w;
    const int b = row / N, i = row - b * N;

    const float m0 = g_stats[b * 128 + lane];
    const float m1 = g_stats[b * 128 + lane + 32];
    const float r0 = g_stats[b * 128 + 64 + lane];
    const float r1 = g_stats[b * 128 + 64 + lane + 32];

    const float* E = emb + (size_t)row * 64;
    float e0 = E[lane], e1 = E[lane + 32];
    float m = (i < nb[b]) ? 1.f : 0.f;
    float n0 = (e0 - m0) * r0 * m;
    float n1 = (e1 - m1) * r1 * m;

    const int pf0 = phi(lane), pf1 = phi(lane + 32);
    g_Ep   [(size_t)row * 64 + pf0] = e0;
    g_Ep   [(size_t)row * 64 + pf1] = e1;
    g_embnP[(size_t)row * 64 + pf0] = n0;
    g_embnP[(size_t)row * 64 + pf1] = n1;
    stile[w][lane]      = n0;
    stile[w][lane + 32] = n1;

    float sq = e0 * e0 + e1 * e1;
    #pragma unroll
    for (int o = 16; o; o >>= 1) sq += __shfl_down_sync(0xffffffffu, sq, o);
    if (lane == 0) g_sq[row] = sq;

    __syncthreads();

    // transposed RNA-tf32 copy: g_EnT[b][f][phi(j)]
    const int base = blockIdx.x * 8;
    const int b0 = base / N, j0 = base % N;   // N % 8 == 0 -> whole CTA same b
    #pragma unroll
    for (int e = 0; e < 2; e++) {
        const int id = t + e * 256;
        const int f = id >> 3, jj = id & 7;
        const int pj = ((jj & 3) << 1) | (jj >> 2);
        g_EnT[(size_t)(b0 * 64 + f) * N + j0 + pj] =
            __uint_as_float(f2tf(stile[jj][f]));
    }
}

// ---------------- Kernel 2: fused Gram -> eltwise -> adj/deg -> SpMM ----------------
#define SEJ 72
#define SET 72
#define SSS 72

__global__ __launch_bounds__(256, 2) void kadj(
    const float* __restrict__ adj_in,
    const int* __restrict__ nb, const float* __restrict__ sigma_p,
    const float* __restrict__ cw, float* __restrict__ adj_out, int N)
{
    extern __shared__ float sm[];
    float*    sEj  = sm;                                   // [2][64][SEJ] emb_j (raw fp32), phi f
    float*    sEnT = sm + 2 * 64 * SEJ;                    // [2][64][SET] embn^T (tf32), phi j
    uint32_t* sS   = (uint32_t*)(sm + 2 * 64 * (SEJ + SET)); // [64][SSS] adj tile (tf32), phi j
    float*    ssqj = sm + 2 * 64 * (SEJ + SET) + 64 * SSS;   // [2][64]
    float*    sdeg = ssqj + 128;                           // [64]

    const int b = blockIdx.y;
    const int ibase = blockIdx.x * 64;
    const int t = threadIdx.x;
    const int w = t >> 5, lane = t & 31;
    const int rowb = (w >> 1) * 16, colb = (w & 1) * 32;
    const int g = lane >> 2, tg = lane & 3;
    const int p0 = (((2 * tg) & 3) << 1) | ((2 * tg) >> 2);
    const int p1 = (((2 * tg + 1) & 3) << 1) | ((2 * tg + 1) >> 2);

    const float inv_sigma = 1.0f / sigma_p[0];
    const float w0 = cw[0], w1 = cw[1];
    const int nbv = nb[b];

    const float* Ep   = g_Ep    + (size_t)b * N * 64;
    const float* EnT  = g_EnT   + (size_t)b * 64 * N;
    const float* SQ   = g_sq    + b * N;
    const float* Ain  = adj_in  + (size_t)b * N * N;
    float*       Aout = adj_out + (size_t)b * N * N;

    const uint32_t u_sEj  = (uint32_t)__cvta_generic_to_shared(sEj);
    const uint32_t u_sEnT = (uint32_t)__cvta_generic_to_shared(sEnT);
    const uint32_t u_ssqj = (uint32_t)__cvta_generic_to_shared(ssqj);

    const int gi0 = ibase + rowb + g;
    const int gi1 = gi0 + 8;

    auto stage = [&](int pb, int jt) {
        const uint32_t bEj = u_sEj  + (uint32_t)(pb * 64 * SEJ) * 4u;
        const uint32_t bEn = u_sEnT + (uint32_t)(pb * 64 * SET) * 4u;
        #pragma unroll
        for (int k = 0; k < 4; k++) {
            const int idx = t + k * 256;
            const int r = idx >> 4, c4 = (idx & 15) << 2;
            cpa16(bEj + (uint32_t)(r * SEJ + c4) * 4u, &Ep [(size_t)(jt + r) * 64 + c4]);
            cpa16(bEn + (uint32_t)(r * SET + c4) * 4u, &EnT[(size_t)r * N + jt + c4]);
        }
        if (t < 16)
            cpa16(u_ssqj + (uint32_t)(pb * 64 + t * 4) * 4u, &SQ[jt + t * 4]);
    };

    stage(0, 0);
    asm volatile("cp.async.commit_group;\n");

    // A fragments (RNA tf32), phi-adjacent pairs -> float2 loads
    uint32_t aF[8][4];
    #pragma unroll
    for (int ks = 0; ks < 8; ks++) {
        float2 q0 = *(const float2*)&Ep[(size_t)gi0 * 64 + ks * 8 + 2 * tg];
        float2 q1 = *(const float2*)&Ep[(size_t)gi1 * 64 + ks * 8 + 2 * tg];
        aF[ks][0] = f2tf(q0.x);
        aF[ks][1] = f2tf(q1.x);
        aF[ks][2] = f2tf(q0.y);
        aF[ks][3] = f2tf(q1.y);
    }
    const float sqi0 = SQ[gi0];
    const float sqi1 = SQ[gi1];
    if (t < 64) sdeg[t] = 0.f;
    const float mi0 = (gi0 < nbv) ? 1.f : 0.f;
    const float mi1 = (gi1 < nbv) ? 1.f : 0.f;

    float opa[4][4];
    #pragma unroll
    for (int n = 0; n < 4; n++)
        #pragma unroll
        for (int k = 0; k < 4; k++) opa[n][k] = 0.f;
    float dg0 = 0.f, dg1 = 0.f;

    asm volatile("cp.async.wait_group 0;\n");
    __syncthreads();

    int pb = 0;
    for (int jt = 0; jt < N; jt += 64, pb ^= 1) {
        if (jt + 64 < N) stage(pb ^ 1, jt + 64);
        asm volatile("cp.async.commit_group;\n");

        // prefetch adj_in
        float2 a01[4], a23[4];
        #pragma unroll
        for (int nt = 0; nt < 4; nt++) {
            const int gj = jt + colb + nt * 8 + 2 * tg;
            a01[nt] = *(const float2*)&Ain[(size_t)gi0 * N + gj];
            a23[nt] = *(const float2*)&Ain[(size_t)gi1 * N + gj];
        }

        const uint32_t* Ej  = (const uint32_t*)(sEj  + pb * 64 * SEJ);
        const uint32_t* EnS = (const uint32_t*)(sEnT + pb * 64 * SET);
        const float*    sqj = ssqj + pb * 64;

        // ---- gemm1: S = emb_i . emb_j^T  (B pairs via LDS.64) ----
        float S[4][4];
        #pragma unroll
        for (int n = 0; n < 4; n++)
            #pragma unroll
            for (int k = 0; k < 4; k++) S[n][k] = 0.f;

        #pragma unroll
        for (int nt = 0; nt < 4; nt++) {
            const int n = colb + nt * 8;
            #pragma unroll
            for (int ks = 0; ks < 8; ks++) {
                uint2 bv = *(const uint2*)&Ej[(n + g) * SEJ + ks * 8 + 2 * tg];
                MMA_TF32(S[nt], aF[ks][0], aF[ks][1], aF[ks][2], aF[ks][3], bv.x, bv.y);
            }
        }

        // ---- eltwise: RBF, combine, mask; write adj; stash S tile (RNA tf32, phi cols) ----
        #pragma unroll
        for (int nt = 0; nt < 4; nt++) {
            const int jl = colb + nt * 8 + 2 * tg;
            const int gj = jt + jl;
            const float sqj0 = sqj[jl], sqj1 = sqj[jl + 1];
            const float mj0 = (gj     < nbv) ? 1.f : 0.f;
            const float mj1 = (gj + 1 < nbv) ? 1.f : 0.f;

            float v00 = (w0 * a01[nt].x + w1 * __expf(-fmaxf(sqi0 + sqj0 - 2.f * S[nt][0], 0.f) * inv_sigma)) * (mi0 * mj0);
            float v01 = (w0 * a01[nt].y + w1 * __expf(-fmaxf(sqi0 + sqj1 - 2.f * S[nt][1], 0.f) * inv_sigma)) * (mi0 * mj1);
            float v10 = (w0 * a23[nt].x + w1 * __expf(-fmaxf(sqi1 + sqj0 - 2.f * S[nt][2], 0.f) * inv_sigma)) * (mi1 * mj0);
            float v11 = (w0 * a23[nt].y + w1 * __expf(-fmaxf(sqi1 + sqj1 - 2.f * S[nt][3], 0.f) * inv_sigma)) * (mi1 * mj1);

            dg0 += v00 + v01;
            dg1 += v10 + v11;

            *(float2*)&Aout[(size_t)gi0 * N + gj] = make_float2(v00, v01);
            *(float2*)&Aout[(size_t)gi1 * N + gj] = make_float2(v10, v11);

            const int cb = colb + nt * 8;
            sS[(rowb + g)     * SSS + cb + p0] = f2tf(v00);
            sS[(rowb + g)     * SSS + cb + p1] = f2tf(v01);
            sS[(rowb + g + 8) * SSS + cb + p0] = f2tf(v10);
            sS[(rowb + g + 8) * SSS + cb + p1] = f2tf(v11);
        }
        // pairwise barrier: only warps (w, w^1) share sS rows
        asm volatile("bar.sync %0, 64;" :: "r"(1 + (w >> 1)) : "memory");

        // ---- gemm2: op_adj += adj_tile @ embn_j  (pure LDS.64 + MMA) ----
        #pragma unroll
        for (int ks = 0; ks < 8; ks++) {
            uint2 A02 = *(const uint2*)&sS[(rowb + g)     * SSS + ks * 8 + 2 * tg];
            uint2 A13 = *(const uint2*)&sS[(rowb + g + 8) * SSS + ks * 8 + 2 * tg];
            #pragma unroll
            for (int nt = 0; nt < 4; nt++) {
                uint2 bv = *(const uint2*)&EnS[(colb + nt * 8 + g) * SET + ks * 8 + 2 * tg];
                MMA_TF32(opa[nt], A02.x, A13.x, A02.y, A13.y, bv.x, bv.y);
            }
        }

        asm volatile("cp.async.wait_group 0;\n");
        __syncthreads();
    }

    // ---- epilogue ----
    dg0 += __shfl_xor_sync(0xffffffffu, dg0, 1);
    dg0 += __shfl_xor_sync(0xffffffffu, dg0, 2);
    dg1 += __shfl_xor_sync(0xffffffffu, dg1, 1);
    dg1 += __shfl_xor_sync(0xffffffffu, dg1, 2);
    if (tg == 0) {
        atomicAdd(&sdeg[rowb + g], dg0);
        atomicAdd(&sdeg[rowb + g + 8], dg1);
    }
    __syncthreads();
    if (t < 64) g_deg[b * N + ibase + t] = sdeg[t];

    // op_adj written phi-permuted (knn consumes permuted layout)
    #pragma unroll
    for (int nt = 0; nt < 4; nt++) {
        const int cb = colb + nt * 8;
        g_opadjP[(size_t)(b * N + gi0) * 64 + cb + p0] = opa[nt][0];
        g_opadjP[(size_t)(b * N + gi0) * 64 + cb + p1] = opa[nt][1];
        g_opadjP[(size_t)(b * N + gi1) * 64 + cb + p0] = opa[nt][2];
        g_opadjP[(size_t)(b * N + gi1) * 64 + cb + p1] = opa[nt][3];
    }
}

// ---------------- Kernel 3: fused 2-stage MLP, split-tf32 MMA (near-fp32) ----------------
#define SWP 136
#define SX  136

__global__ __launch_bounds__(256, 1) void knn(
    const float* __restrict__ embnP, const float* __restrict__ opadjP,
    const float* __restrict__ deg,   const float* __restrict__ Ep,
    const float* __restrict__ W1,    const float* __restrict__ b1,
    const float* __restrict__ W2,    const float* __restrict__ b2,
    float* __restrict__ out)
{
    extern __shared__ float smn[];
    uint32_t* sW1h = (uint32_t*)smn;            // [64][SWP]  W1^T hi (tf32), phi cols
    uint32_t* sW1l = sW1h + 64 * SWP;           // [64][SWP]  W1^T lo
    uint32_t* sW2h = sW1l + 64 * SWP;
    uint32_t* sW2l = sW2h + 64 * SWP;
    float*    sx   = (float*)(sW2l + 64 * SWP); // [128][SX]  x fp32, phi cols
    float*    sb1  = sx + 128 * SX;             // [64]
    float*    sb2  = sb1 + 64;                  // [64]

    const int t = threadIdx.x;
    const int w = t >> 5, lane = t & 31;
    const int g = lane >> 2, tg = lane & 3;
    const int r0 = w * 16;
    const int node0 = blockIdx.x * 128;
    const int p0 = (((2 * tg) & 3) << 1) | ((2 * tg) >> 2);
    const int p1 = (((2 * tg + 1) & 3) << 1) | ((2 * tg + 1) >> 2);

    // stage weights (transposed, phi cols, pre-split hi/lo) + biases
    for (int idx = t; idx < 8192; idx += 256) {
        const int k = idx >> 6, n = idx & 63;
        const int pk = phi(k);
        uint32_t h, l;
        split_tf(W1[idx], h, l);
        sW1h[n * SWP + pk] = h; sW1l[n * SWP + pk] = l;
        split_tf(W2[idx], h, l);
        sW2h[n * SWP + pk] = h; sW2l[n * SWP + pk] = l;
    }
    if (t < 64) { sb1[t] = b1[t]; sb2[t] = b2[t]; }

    // stage x1 = [deg*embn (phi), opadj (phi)]
    for (int idx = t; idx < 2048; idx += 256) {
        const int node = idx >> 4, c = (idx & 15) << 2;
        const float dgv = deg[node0 + node];
        float4 v = *(const float4*)&embnP[(size_t)(node0 + node) * 64 + c];
        v.x *= dgv; v.y *= dgv; v.z *= dgv; v.w *= dgv;
        *(float4*)&sx[node * SX + c] = v;
        *(float4*)&sx[node * SX + 64 + c] =
            *(const float4*)&opadjP[(size_t)(node0 + node) * 64 + c];
    }
    __syncthreads();

    // ---- stage 1: upd = x1 @ W1  (split: hh + lh + hl) ----
    float acc1[8][4];
    #pragma unroll
    for (int n = 0; n < 8; n++)
        #pragma unroll
        for (int k = 0; k < 4; k++) acc1[n][k] = 0.f;

    #pragma unroll
    for (int ks = 0; ks < 16; ks++) {
        float2 A0 = *(const float2*)&sx[(r0 + g)     * SX + ks * 8 + 2 * tg];
        float2 A1 = *(const float2*)&sx[(r0 + g + 8) * SX + ks * 8 + 2 * tg];
        uint32_t ah[4], al[4];
        split_tf(A0.x, ah[0], al[0]);
        split_tf(A1.x, ah[1], al[1]);
        split_tf(A0.y, ah[2], al[2]);
        split_tf(A1.y, ah[3], al[3]);
        #pragma unroll
        for (int nt = 0; nt < 8; nt++) {
            uint2 bh = *(const uint2*)&sW1h[(nt * 8 + g) * SWP + ks * 8 + 2 * tg];
            uint2 bl = *(const uint2*)&sW1l[(nt * 8 + g) * SWP + ks * 8 + 2 * tg];
            MMA_TF32(acc1[nt], ah[0], ah[1], ah[2], ah[3], bh.x, bh.y);
            MMA_TF32(acc1[nt], al[0], al[1], al[2], al[3], bh.x, bh.y);
            MMA_TF32(acc1[nt], ah[0], ah[1], ah[2], ah[3], bl.x, bl.y);
        }
    }
    __syncthreads();   // all warps done reading x1

    // build x2 = [emb_in (phi), upd+b1 (phi)]
    for (int idx = t; idx < 2048; idx += 256) {
        const int node = idx >> 4, c = (idx & 15) << 2;
        *(float4*)&sx[node * SX + c] = *(const float4*)&Ep[(size_t)(node0 + node) * 64 + c];
    }
    #pragma unroll
    for (int nt = 0; nt < 8; nt++) {
        const int f0 = nt * 8 + 2 * tg;
        const int base = 64 + nt * 8;
        sx[(r0 + g)     * SX + base + p0] = acc1[nt][0] + sb1[f0];
        sx[(r0 + g)     * SX + base + p1] = acc1[nt][1] + sb1[f0 + 1];
        sx[(r0 + g + 8) * SX + base + p0] = acc1[nt][2] + sb1[f0];
        sx[(r0 + g + 8) * SX + base + p1] = acc1[nt][3] + sb1[f0 + 1];
    }
    __syncthreads();

    // ---- stage 2: out = relu(x2 @ W2 + b2)  (split) ----
    float acc2[8][4];
    #pragma unroll
    for (int n = 0; n < 8; n++)
        #pragma unroll
        for (int k = 0; k < 4; k++) acc2[n][k] = 0.f;

    #pragma unroll
    for (int ks = 0; ks < 16; ks++) {
        float2 A0 = *(const float2*)&sx[(r0 + g)     * SX + ks * 8 + 2 * tg];
        float2 A1 = *(const float2*)&sx[(r0 + g + 8) * SX + ks * 8 + 2 * tg];
        uint32_t ah[4], al[4];
        split_tf(A0.x, ah[0], al[0]);
        split_tf(A1.x, ah[1], al[1]);
        split_tf(A0.y, ah[2], al[2]);
        split_tf(A1.y, ah[3], al[3]);
        #pragma unroll
        for (int nt = 0; nt < 8; nt++) {
            uint2 bh = *(const uint2*)&sW2h[(nt * 8 + g) * SWP + ks * 8 + 2 * tg];
            uint2 bl = *(const uint2*)&sW2l[(nt * 8 + g) * SWP + ks * 8 + 2 * tg];
            MMA_TF32(acc2[nt], ah[0], ah[1], ah[2], ah[3], bh.x, bh.y);
            MMA_TF32(acc2[nt], al[0], al[1], al[2], al[3], bh.x, bh.y);
            MMA_TF32(acc2[nt], ah[0], ah[1], ah[2], ah[3], bl.x, bl.y);
        }
    }

    #pragma unroll
    for (int nt = 0; nt < 8; nt++) {
        const int f0 = nt * 8 + 2 * tg;
        float o00 = fmaxf(acc2[nt][0] + sb2[f0],     0.f);
        float o01 = fmaxf(acc2[nt][1] + sb2[f0 + 1], 0.f);
        float o10 = fmaxf(acc2[nt][2] + sb2[f0],     0.f);
        float o11 = fmaxf(acc2[nt][3] + sb2[f0 + 1], 0.f);
        *(float2*)&out[(size_t)(node0 + r0 + g)     * 64 + f0] = make_float2(o00, o01);
        *(float2*)&out[(size_t)(node0 + r0 + g + 8) * 64 + f0] = make_float2(o10, o11);
    }
}

// ---------------- launch ----------------
extern "C" void kernel_launch(void* const* d_in, const int* in_sizes, int n_in,
                              void* d_out, int out_size)
{
    const float* emb_in = (const float*)d_in[0];
    const float* adj_in = (const float*)d_in[1];
    // d_in[2] adj_mask: unused (recomputed from batch_nb_nodes)
    const int*   nb     = (const int*)d_in[3];
    const float* sigma  = (const float*)d_in[4];
    const float* cw     = (const float*)d_in[5];
    const float* convW  = (const float*)d_in[6];
    const float* convb  = (const float*)d_in[7];
    const float* nuW    = (const float*)d_in[8];
    const float* nub    = (const float*)d_in[9];

    const int B = in_sizes[3];
    const int N = in_sizes[0] / (B * 64);

    float* out_emb = (float*)d_out;                    // (B,N,64)
    float* out_adj = out_emb + (size_t)B * N * 64;     // (B,N,N)

    float *p_embnP, *p_opadjP, *p_deg, *p_Ep;
    cudaGetSymbolAddress((void**)&p_embnP,  g_embnP);
    cudaGetSymbolAddress((void**)&p_opadjP, g_opadjP);
    cudaGetSymbolAddress((void**)&p_deg,    g_deg);
    cudaGetSymbolAddress((void**)&p_Ep,     g_Ep);

    kstat1<<<dim3(B, 8), 256>>>(emb_in, N);
    kstat2<<<B, 64>>>(nb);
    knorm2<<<(B * N) / 8, 256>>>(emb_in, nb, N);

    const size_t smemAdj = (size_t)(2 * 64 * (SEJ + SET) + 64 * SSS + 128 + 64) * sizeof(float);
    cudaFuncSetAttribute(kadj, cudaFuncAttributeMaxDynamicSharedMemorySize, (int)smemAdj);
    kadj<<<dim3(N / 64, B), 256, smemAdj>>>(adj_in, nb, sigma, cw, out_adj, N);

    const size_t smemNN = (size_t)(4 * 64 * SWP + 128 * SX + 128) * sizeof(float);
    cudaFuncSetAttribute(knn, cudaFuncAttributeMaxDynamicSharedMemorySize, (int)smemNN);
    knn<<<(B * N) / 128, 256, smemNN>>>(p_embnP, p_opadjP, p_deg, p_Ep,
                                        convW, convb, nuW, nub, out_emb);
}